// round 1
// baseline (speedup 1.0000x reference)
#include <cuda_runtime.h>
#include <math.h>

#define B 4
#define P 2048
#define C 512
#define D 1024
#define H 16
#define DH 64

typedef unsigned long long ull;

// ---------------- scratch (static device arrays; no allocation) ----------------
__device__ float g_q[(size_t)B * H * P * DH];   // [B,H,P,DH]
__device__ float g_k[(size_t)B * H * C * DH];   // [B,H,C,DH]
__device__ float g_v[(size_t)B * H * C * DH];   // [B,H,C,DH]
__device__ float g_ctx[(size_t)B * P * D];      // [B,P,D]

// ---------------- packed f32x2 helpers (sm_103a FFMA2 path) ----------------
__device__ __forceinline__ ull dup2(float x) {
    ull r; asm("mov.b64 %0, {%1, %1};" : "=l"(r) : "f"(x)); return r;
}
__device__ __forceinline__ void ffma2(ull& d, ull a, ull b) {
    asm("fma.rn.f32x2 %0, %1, %2, %0;" : "+l"(d) : "l"(a), "l"(b));
}
__device__ __forceinline__ ull mul2(ull a, ull b) {
    ull r; asm("mul.rn.f32x2 %0, %1, %2;" : "=l"(r) : "l"(a), "l"(b)); return r;
}
__device__ __forceinline__ float2 unpk(ull v) {
    float2 f; asm("mov.b64 {%0, %1}, %2;" : "=f"(f.x), "=f"(f.y) : "l"(v)); return f;
}

// =====================================================================
// Kernel 1: projection GEMM.  X[M,D] @ W[D,D] + bias, scaled, written in
// head layout out[b,h,l,dh].  128x128 tile, BK=16, 8x8 per thread,
// f32x2 accumulators paired along N.
// =====================================================================
__global__ void __launch_bounds__(256) proj_gemm(
    const float* __restrict__ X, const float* __restrict__ W,
    const float* __restrict__ bias, float* __restrict__ out,
    int L, float scale)
{
    __shared__ float As[16][132];   // [k][m], padded
    __shared__ float Bs[16][128];   // [k][n]

    const int tid = threadIdx.x;
    const int m0 = blockIdx.y * 128;
    const int n0 = blockIdx.x * 128;
    const int ty = tid >> 4, tx = tid & 15;

    const int arow = tid >> 2;
    const int acol = (tid & 3) << 2;
    const int brow = tid >> 5;
    const int bcol = (tid & 31) << 2;

    ull acc[8][4];
#pragma unroll
    for (int i = 0; i < 8; i++)
#pragma unroll
        for (int j = 0; j < 4; j++) acc[i][j] = 0ull;

    for (int k0 = 0; k0 < D; k0 += 16) {
#pragma unroll
        for (int hh = 0; hh < 2; ++hh) {
            int m = arow + hh * 64;
            float4 a4 = *(const float4*)(X + (size_t)(m0 + m) * D + k0 + acol);
            As[acol + 0][m] = a4.x;
            As[acol + 1][m] = a4.y;
            As[acol + 2][m] = a4.z;
            As[acol + 3][m] = a4.w;
        }
#pragma unroll
        for (int hh = 0; hh < 2; ++hh) {
            int kk = brow + hh * 8;
            *(float4*)(&Bs[kk][bcol]) =
                *(const float4*)(W + (size_t)(k0 + kk) * D + n0 + bcol);
        }
        __syncthreads();

#pragma unroll
        for (int kk = 0; kk < 16; ++kk) {
            float4 a0 = *(const float4*)(&As[kk][ty * 8]);
            float4 a1 = *(const float4*)(&As[kk][ty * 8 + 4]);
            ull ad[8] = {dup2(a0.x), dup2(a0.y), dup2(a0.z), dup2(a0.w),
                         dup2(a1.x), dup2(a1.y), dup2(a1.z), dup2(a1.w)};
            const ull* bp = (const ull*)(&Bs[kk][tx * 8]);
            ull b0 = bp[0], b1 = bp[1], b2 = bp[2], b3 = bp[3];
#pragma unroll
            for (int i = 0; i < 8; i++) {
                ffma2(acc[i][0], ad[i], b0);
                ffma2(acc[i][1], ad[i], b1);
                ffma2(acc[i][2], ad[i], b2);
                ffma2(acc[i][3], ad[i], b3);
            }
        }
        __syncthreads();
    }

#pragma unroll
    for (int i = 0; i < 8; i++) {
        int m = m0 + ty * 8 + i;
        int bb = m / L, l = m % L;
#pragma unroll
        for (int j = 0; j < 4; j++) {
            float2 v = unpk(acc[i][j]);
            int n = n0 + tx * 8 + 2 * j;          // even; n,n+1 share head
            int hh = n >> 6, d0 = n & 63;
            float o0 = (v.x + bias[n]) * scale;
            float o1 = (v.y + bias[n + 1]) * scale;
            size_t base = (((size_t)bb * H + hh) * L + l) * DH + d0;
            out[base] = o0;
            out[base + 1] = o1;
        }
    }
}

// =====================================================================
// Kernel 2: fused edge-masked attention, online softmax.
// Block: (b, h, p-tile of 128).  C processed in chunks of 64.
// Thread (ty,tx) 16x16: owns 8 p-rows (as 4 f32x2 pairs) x 4 (c or dh).
// =====================================================================
#define PT 128
#define CT 64
// smem layout (floats):
//  QsT [64][130], KsT [64][68], Vs [64][68], Ss [64][130], Es [128][65],
//  alpha[128], linv[128]
#define OFF_Q   0
#define OFF_K   (64 * 130)
#define OFF_V   (OFF_K + 64 * 68)
#define OFF_S   (OFF_V + 64 * 68)
#define OFF_E   (OFF_S + 64 * 130)
#define OFF_AL  (OFF_E + 128 * 65)
#define OFF_LI  (OFF_AL + 128)
#define ATTN_SMEM_FLOATS (OFF_LI + 128)
#define ATTN_SMEM_BYTES (ATTN_SMEM_FLOATS * 4)

__global__ void __launch_bounds__(256) attn_kernel(
    const float* __restrict__ q, const float* __restrict__ k,
    const float* __restrict__ v, const float* __restrict__ edge,
    float* __restrict__ ctx)
{
    extern __shared__ float sm[];
    float* QsT = sm + OFF_Q;
    float* KsT = sm + OFF_K;
    float* Vs  = sm + OFF_V;
    float* Ss  = sm + OFF_S;
    float* Es  = sm + OFF_E;
    float* alpha_s = sm + OFF_AL;
    float* linv_s  = sm + OFF_LI;

    const int tid = threadIdx.x;
    const int ty = tid >> 4, tx = tid & 15;
    const int b = blockIdx.z, h = blockIdx.y;
    const int p0 = blockIdx.x * PT;

    const float* qbase = q + (((size_t)b * H + h) * P + p0) * DH;
    const float* kbase = k + (((size_t)b * H + h) * C) * DH;
    const float* vbase = v + (((size_t)b * H + h) * C) * DH;
    const float* ebase = edge + ((size_t)b * P + p0) * C;

    // load Q tile transposed: QsT[d][p]
    for (int i = tid; i < PT * 16; i += 256) {
        int pl = i >> 4, d4 = (i & 15) << 2;
        float4 t = *(const float4*)(qbase + (size_t)pl * DH + d4);
        QsT[(d4 + 0) * 130 + pl] = t.x;
        QsT[(d4 + 1) * 130 + pl] = t.y;
        QsT[(d4 + 2) * 130 + pl] = t.z;
        QsT[(d4 + 3) * 130 + pl] = t.w;
    }

    float m_r = -3.0e38f, l_r = 0.f;   // per-row state (threads 0..127)

    ull ctx2[4][4];
#pragma unroll
    for (int i = 0; i < 4; i++)
#pragma unroll
        for (int j = 0; j < 4; j++) ctx2[i][j] = 0ull;

    for (int c0 = 0; c0 < C; c0 += CT) {
        __syncthreads();   // prior PV done; also covers Q load on iter 0

        // load K^T (KsT[d][c]) and V (Vs[c][d])
        for (int i = tid; i < CT * 16; i += 256) {
            int cl = i >> 4, d4 = (i & 15) << 2;
            float4 t = *(const float4*)(kbase + (size_t)(c0 + cl) * DH + d4);
            KsT[(d4 + 0) * 68 + cl] = t.x;
            KsT[(d4 + 1) * 68 + cl] = t.y;
            KsT[(d4 + 2) * 68 + cl] = t.z;
            KsT[(d4 + 3) * 68 + cl] = t.w;
            float4 tv = *(const float4*)(vbase + (size_t)(c0 + cl) * DH + d4);
            *(float4*)(&Vs[cl * 68 + d4]) = tv;
        }
        // load edge tile Es[p][c]
        for (int i = tid; i < PT * 16; i += 256) {
            int pl = i >> 4, c4 = (i & 15) << 2;
            float4 t = *(const float4*)(ebase + (size_t)pl * C + c0 + c4);
            Es[pl * 65 + c4 + 0] = t.x;
            Es[pl * 65 + c4 + 1] = t.y;
            Es[pl * 65 + c4 + 2] = t.z;
            Es[pl * 65 + c4 + 3] = t.w;
        }
        __syncthreads();

        // ---- S = Q K^T, pairs along p ----
        ull sac[4][4];
#pragma unroll
        for (int i = 0; i < 4; i++)
#pragma unroll
            for (int j = 0; j < 4; j++) sac[i][j] = 0ull;

#pragma unroll 8
        for (int d = 0; d < DH; ++d) {
            const float* qr = QsT + d * 130 + ty * 8;
            ull a0 = *(const ull*)(qr + 0);
            ull a1 = *(const ull*)(qr + 2);
            ull a2 = *(const ull*)(qr + 4);
            ull a3 = *(const ull*)(qr + 6);
            float4 bv = *(const float4*)(KsT + d * 68 + tx * 4);
            ull b0 = dup2(bv.x), b1 = dup2(bv.y), b2 = dup2(bv.z), b3 = dup2(bv.w);
            ffma2(sac[0][0], a0, b0); ffma2(sac[0][1], a0, b1);
            ffma2(sac[0][2], a0, b2); ffma2(sac[0][3], a0, b3);
            ffma2(sac[1][0], a1, b0); ffma2(sac[1][1], a1, b1);
            ffma2(sac[1][2], a1, b2); ffma2(sac[1][3], a1, b3);
            ffma2(sac[2][0], a2, b0); ffma2(sac[2][1], a2, b1);
            ffma2(sac[2][2], a2, b2); ffma2(sac[2][3], a2, b3);
            ffma2(sac[3][0], a3, b0); ffma2(sac[3][1], a3, b1);
            ffma2(sac[3][2], a3, b2); ffma2(sac[3][3], a3, b3);
        }
        // mask + store S transposed: Ss[c][p]
#pragma unroll
        for (int i = 0; i < 4; i++) {
            int pl = ty * 8 + 2 * i;
#pragma unroll
            for (int j = 0; j < 4; j++) {
                int c = tx * 4 + j;
                float2 s = unpk(sac[i][j]);
                float e0 = Es[pl * 65 + c];
                float e1 = Es[(pl + 1) * 65 + c];
                Ss[c * 130 + pl]     = (e0 > 0.f) ? s.x : -1e18f;
                Ss[c * 130 + pl + 1] = (e1 > 0.f) ? s.y : -1e18f;
            }
        }
        __syncthreads();

        // ---- online softmax (one thread per p-row) ----
        if (tid < PT) {
            const int r = tid;
            float cmax = -3.0e38f;
#pragma unroll 8
            for (int c = 0; c < CT; ++c) cmax = fmaxf(cmax, Ss[c * 130 + r]);
            float mn = fmaxf(m_r, cmax);
            float al = __expf(m_r - mn);
            float ls = 0.f;
#pragma unroll 4
            for (int c = 0; c < CT; ++c) {
                float ex = __expf(Ss[c * 130 + r] - mn);
                ls += ex;
                Ss[c * 130 + r] = ex * Es[r * 65 + c];  // numerator gets edge weight
            }
            l_r = l_r * al + ls;       // denominator does NOT get edge weight
            m_r = mn;
            alpha_s[r] = al;
        }
        __syncthreads();

        // ---- rescale ctx, then ctx += P~ @ V ----
        ull al2[4];
#pragma unroll
        for (int i = 0; i < 4; i++)
            al2[i] = *(const ull*)(&alpha_s[ty * 8 + 2 * i]);
#pragma unroll
        for (int i = 0; i < 4; i++)
#pragma unroll
            for (int j = 0; j < 4; j++) ctx2[i][j] = mul2(ctx2[i][j], al2[i]);

#pragma unroll 8
        for (int c = 0; c < CT; ++c) {
            const float* pr = Ss + c * 130 + ty * 8;
            ull a0 = *(const ull*)(pr + 0);
            ull a1 = *(const ull*)(pr + 2);
            ull a2 = *(const ull*)(pr + 4);
            ull a3 = *(const ull*)(pr + 6);
            float4 vv = *(const float4*)(Vs + c * 68 + tx * 4);
            ull b0 = dup2(vv.x), b1 = dup2(vv.y), b2 = dup2(vv.z), b3 = dup2(vv.w);
            ffma2(ctx2[0][0], a0, b0); ffma2(ctx2[0][1], a0, b1);
            ffma2(ctx2[0][2], a0, b2); ffma2(ctx2[0][3], a0, b3);
            ffma2(ctx2[1][0], a1, b0); ffma2(ctx2[1][1], a1, b1);
            ffma2(ctx2[1][2], a1, b2); ffma2(ctx2[1][3], a1, b3);
            ffma2(ctx2[2][0], a2, b0); ffma2(ctx2[2][1], a2, b1);
            ffma2(ctx2[2][2], a2, b2); ffma2(ctx2[2][3], a2, b3);
            ffma2(ctx2[3][0], a3, b0); ffma2(ctx2[3][1], a3, b1);
            ffma2(ctx2[3][2], a3, b2); ffma2(ctx2[3][3], a3, b3);
        }
    }

    // finalize: divide by l and write ctx[b, p, h*64+dh]
    if (tid < PT) linv_s[tid] = 1.0f / l_r;
    __syncthreads();

#pragma unroll
    for (int i = 0; i < 4; i++) {
        int pl = ty * 8 + 2 * i;
        float inv0 = linv_s[pl], inv1 = linv_s[pl + 1];
#pragma unroll
        for (int j = 0; j < 4; j++) {
            float2 cv = unpk(ctx2[i][j]);
            int dh = tx * 4 + j;
            ctx[((size_t)b * P + p0 + pl) * D + h * DH + dh]       = cv.x * inv0;
            ctx[((size_t)b * P + p0 + pl + 1) * D + h * DH + dh]   = cv.y * inv1;
        }
    }
}

// =====================================================================
// Kernel 3: LayerNorm over D=1024, one block per row.
// =====================================================================
__global__ void __launch_bounds__(256) ln_kernel(
    const float* __restrict__ x, const float* __restrict__ gamma,
    const float* __restrict__ beta, float* __restrict__ out)
{
    __shared__ float rs1[8], rs2[8];
    const int row = blockIdx.x;
    const int tid = threadIdx.x;
    const float4 xv = *(const float4*)(x + (size_t)row * D + tid * 4);
    float s1 = xv.x + xv.y + xv.z + xv.w;
    float s2 = xv.x * xv.x + xv.y * xv.y + xv.z * xv.z + xv.w * xv.w;
#pragma unroll
    for (int o = 16; o; o >>= 1) {
        s1 += __shfl_xor_sync(0xffffffffu, s1, o);
        s2 += __shfl_xor_sync(0xffffffffu, s2, o);
    }
    if ((tid & 31) == 0) { rs1[tid >> 5] = s1; rs2[tid >> 5] = s2; }
    __syncthreads();
    if (tid < 32) {
        float t1 = (tid < 8) ? rs1[tid] : 0.f;
        float t2 = (tid < 8) ? rs2[tid] : 0.f;
#pragma unroll
        for (int o = 4; o; o >>= 1) {
            t1 += __shfl_xor_sync(0xffffffffu, t1, o);
            t2 += __shfl_xor_sync(0xffffffffu, t2, o);
        }
        if (tid == 0) { rs1[0] = t1; rs2[0] = t2; }
    }
    __syncthreads();
    const float mu = rs1[0] * (1.0f / D);
    const float var = fmaxf(rs2[0] * (1.0f / D) - mu * mu, 0.f);
    const float r = rsqrtf(var + 1e-6f);
    const float4 g = *(const float4*)(gamma + tid * 4);
    const float4 bt = *(const float4*)(beta + tid * 4);
    float4 o;
    o.x = (xv.x - mu) * r * g.x + bt.x;
    o.y = (xv.y - mu) * r * g.y + bt.y;
    o.z = (xv.z - mu) * r * g.z + bt.z;
    o.w = (xv.w - mu) * r * g.w + bt.w;
    *(float4*)(out + (size_t)row * D + tid * 4) = o;
}

// =====================================================================
extern "C" void kernel_launch(void* const* d_in, const int* in_sizes, int n_in,
                              void* d_out, int out_size)
{
    const float* para    = (const float*)d_in[0];
    const float* cluster = (const float*)d_in[1];
    const float* edge    = (const float*)d_in[2];
    const float* Wq = (const float*)d_in[3];
    const float* bq = (const float*)d_in[4];
    const float* Wk = (const float*)d_in[5];
    const float* bk = (const float*)d_in[6];
    const float* Wv = (const float*)d_in[7];
    const float* bv = (const float*)d_in[8];
    const float* gamma = (const float*)d_in[9];
    const float* beta  = (const float*)d_in[10];
    float* out = (float*)d_out;

    float *qp, *kp, *vp, *cp;
    cudaGetSymbolAddress((void**)&qp, g_q);
    cudaGetSymbolAddress((void**)&kp, g_k);
    cudaGetSymbolAddress((void**)&vp, g_v);
    cudaGetSymbolAddress((void**)&cp, g_ctx);

    cudaFuncSetAttribute(attn_kernel,
                         cudaFuncAttributeMaxDynamicSharedMemorySize,
                         ATTN_SMEM_BYTES);

    // projections: Q (scaled 1/sqrt(DH)), K, V
    proj_gemm<<<dim3(D / 128, (B * P) / 128), 256>>>(para, Wq, bq, qp, P, 0.125f);
    proj_gemm<<<dim3(D / 128, (B * C) / 128), 256>>>(cluster, Wk, bk, kp, C, 1.0f);
    proj_gemm<<<dim3(D / 128, (B * C) / 128), 256>>>(cluster, Wv, bv, vp, C, 1.0f);

    // fused masked attention
    attn_kernel<<<dim3(P / PT, H, B), 256, ATTN_SMEM_BYTES>>>(qp, kp, vp, edge, cp);

    // layernorm
    ln_kernel<<<B * P, 256>>>(cp, gamma, beta, out);
}

// round 2
// speedup vs baseline: 1.2693x; 1.2693x over previous
#include <cuda_runtime.h>
#include <math.h>

#define B 4
#define P 2048
#define C 512
#define D 1024
#define H 16
#define DH 64

typedef unsigned long long ull;

// ---------------- scratch ----------------
__device__ float g_q[(size_t)B * H * P * DH];
__device__ float g_k[(size_t)B * H * C * DH];
__device__ float g_v[(size_t)B * H * C * DH];
__device__ float g_ctx[(size_t)B * P * D];

// ---------------- packed f32x2 helpers ----------------
__device__ __forceinline__ ull dup2(float x) {
    ull r; asm("mov.b64 %0, {%1, %1};" : "=l"(r) : "f"(x)); return r;
}
__device__ __forceinline__ ull pack2(float lo, float hi) {
    ull r; asm("mov.b64 %0, {%1, %2};" : "=l"(r) : "f"(lo), "f"(hi)); return r;
}
__device__ __forceinline__ void ffma2(ull& d, ull a, ull b) {
    asm("fma.rn.f32x2 %0, %1, %2, %0;" : "+l"(d) : "l"(a), "l"(b));
}
__device__ __forceinline__ ull mul2(ull a, ull b) {
    ull r; asm("mul.rn.f32x2 %0, %1, %2;" : "=l"(r) : "l"(a), "l"(b)); return r;
}
__device__ __forceinline__ float2 unpk(ull v) {
    float2 f; asm("mov.b64 {%0, %1}, %2;" : "=f"(f.x), "=f"(f.y) : "l"(v)); return f;
}

// =====================================================================
// Kernel 1: all three projections in ONE launch (flat grid, 768 CTAs).
// 128x128 tile, BK=16, 8x8 per thread, register-staged double buffer,
// 2 CTAs/SM.  Output scattered into head layout [b,h,l,dh].
// =====================================================================
__global__ void __launch_bounds__(256, 2) proj_gemm(
    const float* __restrict__ para, const float* __restrict__ cluster,
    const float* __restrict__ Wq, const float* __restrict__ bq,
    const float* __restrict__ Wk, const float* __restrict__ bk,
    const float* __restrict__ Wv, const float* __restrict__ bv,
    float* __restrict__ qout, float* __restrict__ kout, float* __restrict__ vout)
{
    __shared__ float As[2][16][132];
    __shared__ float Bs[2][16][128];

    const int bid = blockIdx.x;
    const float *X, *W, *bias; float* out;
    int mblk, Lsh; float scale;
    if (bid < 512)      { X = para;    W = Wq; bias = bq; out = qout; Lsh = 11; scale = 0.125f; mblk = bid >> 3; }
    else if (bid < 640) { X = cluster; W = Wk; bias = bk; out = kout; Lsh = 9;  scale = 1.0f;   mblk = (bid - 512) >> 3; }
    else                { X = cluster; W = Wv; bias = bv; out = vout; Lsh = 9;  scale = 1.0f;   mblk = (bid - 640) >> 3; }
    const int n0 = (bid & 7) * 128;
    const int m0 = mblk * 128;

    const int tid = threadIdx.x;
    const int ty = tid >> 4, tx = tid & 15;
    const int arow = tid >> 2;
    const int acol = (tid & 3) << 2;
    const int brow = tid >> 5;
    const int bcol = (tid & 31) << 2;

    const float* Xp = X + (size_t)(m0 + arow) * D + acol;
    const float* Wp = W + (size_t)brow * D + n0 + bcol;

    // preload tile 0
    {
        float4 a0 = *(const float4*)(Xp);
        float4 a1 = *(const float4*)(Xp + (size_t)64 * D);
        float4 w0 = *(const float4*)(Wp);
        float4 w1 = *(const float4*)(Wp + (size_t)8 * D);
        As[0][acol + 0][arow] = a0.x; As[0][acol + 1][arow] = a0.y;
        As[0][acol + 2][arow] = a0.z; As[0][acol + 3][arow] = a0.w;
        As[0][acol + 0][arow + 64] = a1.x; As[0][acol + 1][arow + 64] = a1.y;
        As[0][acol + 2][arow + 64] = a1.z; As[0][acol + 3][arow + 64] = a1.w;
        *(float4*)(&Bs[0][brow][bcol]) = w0;
        *(float4*)(&Bs[0][brow + 8][bcol]) = w1;
    }
    __syncthreads();

    ull acc[8][4];
#pragma unroll
    for (int i = 0; i < 8; i++)
#pragma unroll
        for (int j = 0; j < 4; j++) acc[i][j] = 0ull;

    for (int k0 = 0; k0 < D; k0 += 16) {
        const int cur = (k0 >> 4) & 1;
        float4 na0, na1, nw0, nw1;
        const bool more = (k0 + 16) < D;
        if (more) {
            na0 = *(const float4*)(Xp + k0 + 16);
            na1 = *(const float4*)(Xp + (size_t)64 * D + k0 + 16);
            nw0 = *(const float4*)(Wp + (size_t)(k0 + 16) * D);
            nw1 = *(const float4*)(Wp + (size_t)(k0 + 24) * D);
        }

#pragma unroll
        for (int kk = 0; kk < 16; ++kk) {
            float4 x0 = *(const float4*)(&As[cur][kk][ty * 8]);
            float4 x1 = *(const float4*)(&As[cur][kk][ty * 8 + 4]);
            ull ad[8] = {dup2(x0.x), dup2(x0.y), dup2(x0.z), dup2(x0.w),
                         dup2(x1.x), dup2(x1.y), dup2(x1.z), dup2(x1.w)};
            const float* bp = &Bs[cur][kk][0];
            ull b0 = *(const ull*)(bp + tx * 4);
            ull b1 = *(const ull*)(bp + tx * 4 + 2);
            ull b2 = *(const ull*)(bp + 64 + tx * 4);
            ull b3 = *(const ull*)(bp + 64 + tx * 4 + 2);
#pragma unroll
            for (int i = 0; i < 8; i++) {
                ffma2(acc[i][0], ad[i], b0);
                ffma2(acc[i][1], ad[i], b1);
                ffma2(acc[i][2], ad[i], b2);
                ffma2(acc[i][3], ad[i], b3);
            }
        }

        if (more) {
            const int nb = cur ^ 1;
            As[nb][acol + 0][arow] = na0.x; As[nb][acol + 1][arow] = na0.y;
            As[nb][acol + 2][arow] = na0.z; As[nb][acol + 3][arow] = na0.w;
            As[nb][acol + 0][arow + 64] = na1.x; As[nb][acol + 1][arow + 64] = na1.y;
            As[nb][acol + 2][arow + 64] = na1.z; As[nb][acol + 3][arow + 64] = na1.w;
            *(float4*)(&Bs[nb][brow][bcol]) = nw0;
            *(float4*)(&Bs[nb][brow + 8][bcol]) = nw1;
        }
        __syncthreads();
    }

    const int Lm = (1 << Lsh) - 1;
#pragma unroll
    for (int i = 0; i < 8; i++) {
        int m = m0 + ty * 8 + i;
        int bb = m >> Lsh, l = m & Lm;
#pragma unroll
        for (int j = 0; j < 4; j++) {
            float2 v = unpk(acc[i][j]);
            int n = n0 + ((j < 2) ? (tx * 4 + 2 * j) : (64 + tx * 4 + 2 * (j - 2)));
            int hh = n >> 6, d0 = n & 63;
            float o0 = (v.x + bias[n]) * scale;
            float o1 = (v.y + bias[n + 1]) * scale;
            size_t base = (((size_t)bb * H + hh) * (size_t)(Lm + 1) + l) * DH + d0;
            out[base] = o0;
            out[base + 1] = o1;
        }
    }
}

// =====================================================================
// Kernel 2: fused edge-masked attention, 512 threads, register softmax
// via shfl across the 16 tx lanes.  Each thread: 4 p-rows x 4 (c|dh).
// =====================================================================
#define PT 128
#define CT 64
#define QS 130
#define KS 68
#define VS 68
#define SSD 130
#define ES 68
#define OFF_K (64 * QS)
#define OFF_V (OFF_K + 64 * KS)
#define OFF_S (OFF_V + 64 * VS)
#define OFF_E (OFF_S + 64 * SSD)
#define ATTN_SMEM_FLOATS (OFF_E + 128 * ES)
#define ATTN_SMEM_BYTES (ATTN_SMEM_FLOATS * 4)

__global__ void __launch_bounds__(512) attn_kernel(
    const float* __restrict__ q, const float* __restrict__ k,
    const float* __restrict__ v, const float* __restrict__ edge,
    float* __restrict__ ctx)
{
    extern __shared__ float sm[];
    float* QsT = sm;
    float* KsT = sm + OFF_K;
    float* Vs  = sm + OFF_V;
    float* Ss  = sm + OFF_S;
    float* Es  = sm + OFF_E;

    const int tid = threadIdx.x;
    const int ty = tid >> 4, tx = tid & 15;
    const int b = blockIdx.z, h = blockIdx.y;
    const int p0 = blockIdx.x * PT;

    const float* qbase = q + (((size_t)b * H + h) * P + p0) * DH;
    const float* kbase = k + (((size_t)b * H + h) * C) * DH;
    const float* vbase = v + (((size_t)b * H + h) * C) * DH;
    const float* ebase = edge + ((size_t)b * P + p0) * C;

    // Q tile transposed: QsT[d][p]
    for (int i = tid; i < PT * 16; i += 512) {
        int pl = i >> 4, d4 = (i & 15) << 2;
        float4 t = *(const float4*)(qbase + (size_t)pl * DH + d4);
        QsT[(d4 + 0) * QS + pl] = t.x;
        QsT[(d4 + 1) * QS + pl] = t.y;
        QsT[(d4 + 2) * QS + pl] = t.z;
        QsT[(d4 + 3) * QS + pl] = t.w;
    }

    float m_r[4] = {-3.0e38f, -3.0e38f, -3.0e38f, -3.0e38f};
    float l_r[4] = {0.f, 0.f, 0.f, 0.f};
    ull ctx2[2][4];
#pragma unroll
    for (int i = 0; i < 2; i++)
#pragma unroll
        for (int j = 0; j < 4; j++) ctx2[i][j] = 0ull;

    for (int c0 = 0; c0 < C; c0 += CT) {
        __syncthreads();   // previous PV done before overwriting K/V/E (and Q load on iter 0)

        for (int i = tid; i < CT * 16; i += 512) {
            int cl = i >> 4, d4 = (i & 15) << 2;
            float4 t = *(const float4*)(kbase + (size_t)(c0 + cl) * DH + d4);
            KsT[(d4 + 0) * KS + cl] = t.x;
            KsT[(d4 + 1) * KS + cl] = t.y;
            KsT[(d4 + 2) * KS + cl] = t.z;
            KsT[(d4 + 3) * KS + cl] = t.w;
            float4 tv = *(const float4*)(vbase + (size_t)(c0 + cl) * DH + d4);
            *(float4*)(&Vs[cl * VS + d4]) = tv;
        }
        for (int i = tid; i < PT * 16; i += 512) {
            int pl = i >> 4, c4 = (i & 15) << 2;
            *(float4*)(&Es[pl * ES + c4]) =
                *(const float4*)(ebase + (size_t)pl * C + c0 + c4);
        }
        __syncthreads();

        // ---- S = Q K^T ----
        ull sac[2][4];
#pragma unroll
        for (int i = 0; i < 2; i++)
#pragma unroll
            for (int j = 0; j < 4; j++) sac[i][j] = 0ull;

#pragma unroll 8
        for (int d = 0; d < DH; ++d) {
            const float* qr = QsT + d * QS + ty * 4;
            ull a0 = *(const ull*)(qr);
            ull a1 = *(const ull*)(qr + 2);
            float4 bv = *(const float4*)(KsT + d * KS + tx * 4);
            ull b0 = dup2(bv.x), b1 = dup2(bv.y), b2 = dup2(bv.z), b3 = dup2(bv.w);
            ffma2(sac[0][0], a0, b0); ffma2(sac[0][1], a0, b1);
            ffma2(sac[0][2], a0, b2); ffma2(sac[0][3], a0, b3);
            ffma2(sac[1][0], a1, b0); ffma2(sac[1][1], a1, b1);
            ffma2(sac[1][2], a1, b2); ffma2(sac[1][3], a1, b3);
        }

        // ---- register softmax (shfl over tx) ----
        float vals[4][4];
#pragma unroll
        for (int j = 0; j < 4; j++) {
            float2 t0 = unpk(sac[0][j]); vals[0][j] = t0.x; vals[1][j] = t0.y;
            float2 t1 = unpk(sac[1][j]); vals[2][j] = t1.x; vals[3][j] = t1.y;
        }
        float alpha[4];
#pragma unroll
        for (int r = 0; r < 4; r++) {
            float4 ew = *(const float4*)(Es + (ty * 4 + r) * ES + tx * 4);
            float e0 = ew.x, e1 = ew.y, e2 = ew.z, e3 = ew.w;
            vals[r][0] = (e0 > 0.f) ? vals[r][0] : -1e18f;
            vals[r][1] = (e1 > 0.f) ? vals[r][1] : -1e18f;
            vals[r][2] = (e2 > 0.f) ? vals[r][2] : -1e18f;
            vals[r][3] = (e3 > 0.f) ? vals[r][3] : -1e18f;
            float mx = fmaxf(fmaxf(vals[r][0], vals[r][1]),
                             fmaxf(vals[r][2], vals[r][3]));
#pragma unroll
            for (int o = 1; o < 16; o <<= 1)
                mx = fmaxf(mx, __shfl_xor_sync(0xffffffffu, mx, o));
            float mn = fmaxf(m_r[r], mx);
            alpha[r] = __expf(m_r[r] - mn);
            m_r[r] = mn;
            float ex0 = __expf(vals[r][0] - mn);
            float ex1 = __expf(vals[r][1] - mn);
            float ex2 = __expf(vals[r][2] - mn);
            float ex3 = __expf(vals[r][3] - mn);
            float s = (ex0 + ex1) + (ex2 + ex3);
            vals[r][0] = ex0 * e0; vals[r][1] = ex1 * e1;
            vals[r][2] = ex2 * e2; vals[r][3] = ex3 * e3;
#pragma unroll
            for (int o = 1; o < 16; o <<= 1)
                s += __shfl_xor_sync(0xffffffffu, s, o);
            l_r[r] = l_r[r] * alpha[r] + s;
        }
        // store weighted probabilities transposed: Ss[c][p]
#pragma unroll
        for (int j = 0; j < 4; j++) {
            int c = tx * 4 + j;
            *(ull*)(&Ss[c * SSD + ty * 4])     = pack2(vals[0][j], vals[1][j]);
            *(ull*)(&Ss[c * SSD + ty * 4 + 2]) = pack2(vals[2][j], vals[3][j]);
        }
        __syncthreads();

        // ---- rescale ctx, then ctx += P~ @ V ----
        ull al01 = pack2(alpha[0], alpha[1]);
        ull al23 = pack2(alpha[2], alpha[3]);
#pragma unroll
        for (int j = 0; j < 4; j++) {
            ctx2[0][j] = mul2(ctx2[0][j], al01);
            ctx2[1][j] = mul2(ctx2[1][j], al23);
        }
#pragma unroll 8
        for (int c = 0; c < CT; ++c) {
            const float* pr = Ss + c * SSD + ty * 4;
            ull a0 = *(const ull*)(pr);
            ull a1 = *(const ull*)(pr + 2);
            float4 vv = *(const float4*)(Vs + c * VS + tx * 4);
            ull b0 = dup2(vv.x), b1 = dup2(vv.y), b2 = dup2(vv.z), b3 = dup2(vv.w);
            ffma2(ctx2[0][0], a0, b0); ffma2(ctx2[0][1], a0, b1);
            ffma2(ctx2[0][2], a0, b2); ffma2(ctx2[0][3], a0, b3);
            ffma2(ctx2[1][0], a1, b0); ffma2(ctx2[1][1], a1, b1);
            ffma2(ctx2[1][2], a1, b2); ffma2(ctx2[1][3], a1, b3);
        }
    }

    float inv0 = 1.0f / l_r[0], inv1 = 1.0f / l_r[1];
    float inv2 = 1.0f / l_r[2], inv3 = 1.0f / l_r[3];
#pragma unroll
    for (int j = 0; j < 4; j++) {
        float2 c0v = unpk(ctx2[0][j]);
        float2 c1v = unpk(ctx2[1][j]);
        int dh = tx * 4 + j;
        size_t base = ((size_t)b * P + p0 + ty * 4) * D + h * DH + dh;
        ctx[base]           = c0v.x * inv0;
        ctx[base + D]       = c0v.y * inv1;
        ctx[base + 2 * (size_t)D] = c1v.x * inv2;
        ctx[base + 3 * (size_t)D] = c1v.y * inv3;
    }
}

// =====================================================================
// Kernel 3: LayerNorm over D=1024, one block per row.
// =====================================================================
__global__ void __launch_bounds__(256) ln_kernel(
    const float* __restrict__ x, const float* __restrict__ gamma,
    const float* __restrict__ beta, float* __restrict__ out)
{
    __shared__ float rs1[8], rs2[8];
    const int row = blockIdx.x;
    const int tid = threadIdx.x;
    const float4 xv = *(const float4*)(x + (size_t)row * D + tid * 4);
    float s1 = xv.x + xv.y + xv.z + xv.w;
    float s2 = xv.x * xv.x + xv.y * xv.y + xv.z * xv.z + xv.w * xv.w;
#pragma unroll
    for (int o = 16; o; o >>= 1) {
        s1 += __shfl_xor_sync(0xffffffffu, s1, o);
        s2 += __shfl_xor_sync(0xffffffffu, s2, o);
    }
    if ((tid & 31) == 0) { rs1[tid >> 5] = s1; rs2[tid >> 5] = s2; }
    __syncthreads();
    if (tid < 32) {
        float t1 = (tid < 8) ? rs1[tid] : 0.f;
        float t2 = (tid < 8) ? rs2[tid] : 0.f;
#pragma unroll
        for (int o = 4; o; o >>= 1) {
            t1 += __shfl_xor_sync(0xffffffffu, t1, o);
            t2 += __shfl_xor_sync(0xffffffffu, t2, o);
        }
        if (tid == 0) { rs1[0] = t1; rs2[0] = t2; }
    }
    __syncthreads();
    const float mu = rs1[0] * (1.0f / D);
    const float var = fmaxf(rs2[0] * (1.0f / D) - mu * mu, 0.f);
    const float r = rsqrtf(var + 1e-6f);
    const float4 g = *(const float4*)(gamma + tid * 4);
    const float4 bt = *(const float4*)(beta + tid * 4);
    float4 o;
    o.x = (xv.x - mu) * r * g.x + bt.x;
    o.y = (xv.y - mu) * r * g.y + bt.y;
    o.z = (xv.z - mu) * r * g.z + bt.z;
    o.w = (xv.w - mu) * r * g.w + bt.w;
    *(float4*)(out + (size_t)row * D + tid * 4) = o;
}

// =====================================================================
extern "C" void kernel_launch(void* const* d_in, const int* in_sizes, int n_in,
                              void* d_out, int out_size)
{
    const float* para    = (const float*)d_in[0];
    const float* cluster = (const float*)d_in[1];
    const float* edge    = (const float*)d_in[2];
    const float* Wq = (const float*)d_in[3];
    const float* bq = (const float*)d_in[4];
    const float* Wk = (const float*)d_in[5];
    const float* bk = (const float*)d_in[6];
    const float* Wv = (const float*)d_in[7];
    const float* bv = (const float*)d_in[8];
    const float* gamma = (const float*)d_in[9];
    const float* beta  = (const float*)d_in[10];
    float* out = (float*)d_out;

    float *qp, *kp, *vp, *cp;
    cudaGetSymbolAddress((void**)&qp, g_q);
    cudaGetSymbolAddress((void**)&kp, g_k);
    cudaGetSymbolAddress((void**)&vp, g_v);
    cudaGetSymbolAddress((void**)&cp, g_ctx);

    cudaFuncSetAttribute(attn_kernel,
                         cudaFuncAttributeMaxDynamicSharedMemorySize,
                         ATTN_SMEM_BYTES);

    // all projections in one wave-friendly launch
    proj_gemm<<<768, 256>>>(para, cluster, Wq, bq, Wk, bk, Wv, bv, qp, kp, vp);

    // fused masked attention
    attn_kernel<<<dim3(P / PT, H, B), 512, ATTN_SMEM_BYTES>>>(qp, kp, vp, edge, cp);

    // layernorm
    ln_kernel<<<B * P, 256>>>(cp, gamma, beta, out);
}

// round 4
// speedup vs baseline: 1.6539x; 1.3030x over previous
#include <cuda_runtime.h>
#include <cuda_bf16.h>
#include <math.h>
#include <stdint.h>

#define B 4
#define P 2048
#define C 512
#define D 1024
#define H 16
#define DH 64

typedef unsigned long long ull;

// ---------------- scratch (static device arrays) ----------------
__device__ float g_q[(size_t)B * H * P * DH];
__device__ float g_k[(size_t)B * H * C * DH];
__device__ float g_v[(size_t)B * H * C * DH];
__device__ float g_ctx[(size_t)B * P * D];
__device__ __nv_bfloat16 g_pa_hi[(size_t)B * P * D];
__device__ __nv_bfloat16 g_pa_lo[(size_t)B * P * D];
__device__ __nv_bfloat16 g_cl_hi[(size_t)B * C * D];
__device__ __nv_bfloat16 g_cl_lo[(size_t)B * C * D];
__device__ __nv_bfloat16 g_wt_hi[(size_t)3 * D * D];
__device__ __nv_bfloat16 g_wt_lo[(size_t)3 * D * D];

// ---------------- packed f32x2 helpers (attn kernel) ----------------
__device__ __forceinline__ ull dup2(float x) {
    ull r; asm("mov.b64 %0, {%1, %1};" : "=l"(r) : "f"(x)); return r;
}
__device__ __forceinline__ ull pack2(float lo, float hi) {
    ull r; asm("mov.b64 %0, {%1, %2};" : "=l"(r) : "f"(lo), "f"(hi)); return r;
}
__device__ __forceinline__ void ffma2(ull& d, ull a, ull b) {
    asm("fma.rn.f32x2 %0, %1, %2, %0;" : "+l"(d) : "l"(a), "l"(b));
}
__device__ __forceinline__ ull mul2(ull a, ull b) {
    ull r; asm("mul.rn.f32x2 %0, %1, %2;" : "=l"(r) : "l"(a), "l"(b)); return r;
}
__device__ __forceinline__ float2 unpk(ull v) {
    float2 f; asm("mov.b64 {%0, %1}, %2;" : "=f"(f.x), "=f"(f.y) : "l"(v)); return f;
}

__device__ __forceinline__ uint32_t smem_u32(const void* p) {
    uint32_t a;
    asm("{ .reg .u64 t; cvta.to.shared.u64 t, %1; cvt.u32.u64 %0, t; }"
        : "=r"(a) : "l"(p));
    return a;
}

// ---------------- mma.sync helpers (baseline PTX, no sm_103a features) ----------------
__device__ __forceinline__ void ldsm_x4(uint32_t& r0, uint32_t& r1,
                                        uint32_t& r2, uint32_t& r3, uint32_t a) {
    asm volatile("ldmatrix.sync.aligned.m8n8.x4.shared.b16 {%0,%1,%2,%3}, [%4];"
                 : "=r"(r0), "=r"(r1), "=r"(r2), "=r"(r3) : "r"(a));
}
__device__ __forceinline__ void ldsm_x2(uint32_t& r0, uint32_t& r1, uint32_t a) {
    asm volatile("ldmatrix.sync.aligned.m8n8.x2.shared.b16 {%0,%1}, [%2];"
                 : "=r"(r0), "=r"(r1) : "r"(a));
}
__device__ __forceinline__ void mma16816(float* d, const uint32_t* a,
                                         const uint32_t* b) {
    asm volatile(
        "mma.sync.aligned.m16n8k16.row.col.f32.bf16.bf16.f32 "
        "{%0,%1,%2,%3}, {%4,%5,%6,%7}, {%8,%9}, {%0,%1,%2,%3};"
        : "+f"(d[0]), "+f"(d[1]), "+f"(d[2]), "+f"(d[3])
        : "r"(a[0]), "r"(a[1]), "r"(a[2]), "r"(a[3]), "r"(b[0]), "r"(b[1]));
}
__device__ __forceinline__ void cp16(uint32_t dst, const void* src) {
    asm volatile("cp.async.cg.shared.global [%0], [%1], 16;"
                 :: "r"(dst), "l"(src));
}
#define CP_COMMIT() asm volatile("cp.async.commit_group;" ::: "memory")
#define CP_WAIT0()  asm volatile("cp.async.wait_group 0;" ::: "memory")

// =====================================================================
// Prep kernel 1: split fp32 -> (hi, lo) bf16, elementwise.
// =====================================================================
__global__ void __launch_bounds__(256) cvt_split(
    const float* __restrict__ x, __nv_bfloat16* __restrict__ hi,
    __nv_bfloat16* __restrict__ lo)
{
    size_t i = ((size_t)blockIdx.x * 256 + threadIdx.x) * 4;
    float4 v = *(const float4*)(x + i);
    __nv_bfloat16 h0 = __float2bfloat16(v.x);
    __nv_bfloat16 h1 = __float2bfloat16(v.y);
    __nv_bfloat16 h2 = __float2bfloat16(v.z);
    __nv_bfloat16 h3 = __float2bfloat16(v.w);
    __nv_bfloat162 hp0{h0, h1}, hp1{h2, h3};
    __nv_bfloat162 lp0{__float2bfloat16(v.x - __bfloat162float(h0)),
                       __float2bfloat16(v.y - __bfloat162float(h1))};
    __nv_bfloat162 lp1{__float2bfloat16(v.z - __bfloat162float(h2)),
                       __float2bfloat16(v.w - __bfloat162float(h3))};
    *(__nv_bfloat162*)(hi + i) = hp0;
    *(__nv_bfloat162*)(hi + i + 2) = hp1;
    *(__nv_bfloat162*)(lo + i) = lp0;
    *(__nv_bfloat162*)(lo + i + 2) = lp1;
}

// =====================================================================
// Prep kernel 2: transpose W [K,N] -> Wt [N,K] and split hi/lo bf16.
// =====================================================================
__global__ void __launch_bounds__(256) wt_split(
    const float* __restrict__ Wq, const float* __restrict__ Wk,
    const float* __restrict__ Wv, __nv_bfloat16* __restrict__ hi,
    __nv_bfloat16* __restrict__ lo)
{
    __shared__ float t[32][33];
    const float* W = (blockIdx.z == 0) ? Wq : (blockIdx.z == 1) ? Wk : Wv;
    size_t ooff = (size_t)blockIdx.z * D * D;
    int k0 = blockIdx.x * 32, n0 = blockIdx.y * 32;
    int tx = threadIdx.x & 31, ty = threadIdx.x >> 5;
#pragma unroll
    for (int j = 0; j < 4; j++)
        t[ty + j * 8][tx] = W[(size_t)(k0 + ty + j * 8) * D + n0 + tx];
    __syncthreads();
#pragma unroll
    for (int j = 0; j < 4; j++) {
        int n = n0 + ty + j * 8, kk = k0 + tx;
        float v = t[tx][ty + j * 8];
        __nv_bfloat16 h = __float2bfloat16(v);
        hi[ooff + (size_t)n * D + kk] = h;
        lo[ooff + (size_t)n * D + kk] = __float2bfloat16(v - __bfloat162float(h));
    }
}

// =====================================================================
// Kernel: projection GEMM via mma.sync bf16 split (3-pass fp32 emu).
// 128x128 tile, K chunks of 32, cp.async double buffer.
// Warps: 2(m) x 4(n); each warp 64x32 = 4x4 m16n8k16 tiles.
// =====================================================================
#define SST 40                       // smem row stride in bf16 (80B, conflict-free)
#define ARR_B (128 * SST * 2)        // 10240 bytes per array
#define STAGE_B (4 * ARR_B)          // 40960
#define PROJ_SMEM_BYTES (2 * STAGE_B)

__global__ void __launch_bounds__(256, 2) proj_mma(
    const __nv_bfloat16* __restrict__ pa_hi, const __nv_bfloat16* __restrict__ pa_lo,
    const __nv_bfloat16* __restrict__ cl_hi, const __nv_bfloat16* __restrict__ cl_lo,
    const __nv_bfloat16* __restrict__ wt_hi, const __nv_bfloat16* __restrict__ wt_lo,
    const float* __restrict__ bq, const float* __restrict__ bk,
    const float* __restrict__ bv,
    float* __restrict__ qout, float* __restrict__ kout, float* __restrict__ vout)
{
    extern __shared__ char smem[];
    const uint32_t sbase = smem_u32(smem);
    const int tid = threadIdx.x;
    const int wid = tid >> 5, lane = tid & 31;

    const int bid = blockIdx.x;
    const __nv_bfloat16 *Xh, *Xl, *Wh, *Wl;
    const float* bias; float* out;
    int mblk, Lsh; float scale;
    if (bid < 512) {
        Xh = pa_hi; Xl = pa_lo; Wh = wt_hi; Wl = wt_lo;
        bias = bq; out = qout; Lsh = 11; scale = 0.125f; mblk = bid >> 3;
    } else if (bid < 640) {
        Xh = cl_hi; Xl = cl_lo; Wh = wt_hi + (size_t)D * D; Wl = wt_lo + (size_t)D * D;
        bias = bk; out = kout; Lsh = 9; scale = 1.0f; mblk = (bid - 512) >> 3;
    } else {
        Xh = cl_hi; Xl = cl_lo; Wh = wt_hi + (size_t)2 * D * D; Wl = wt_lo + (size_t)2 * D * D;
        bias = bv; out = vout; Lsh = 9; scale = 1.0f; mblk = (bid - 640) >> 3;
    }
    const int n0 = (bid & 7) * 128;
    const int m0 = mblk * 128;

    const int wm = wid >> 2;          // 0..1 (m half)
    const int wn = wid & 3;           // 0..3 (n quarter)

    // cp.async mapping: per array, 512 x 16B; this thread does idx=tid, tid+256
    const int r0 = tid >> 2, s0 = (tid & 3);          // row, 16B-seg
    const int r1 = (tid + 256) >> 2, s1 = ((tid + 256) & 3);

    auto stage_load = [&](int stg, int k0) {
        const uint32_t sb = sbase + (uint32_t)stg * STAGE_B;
        const __nv_bfloat16* srcs[4] = {Xh, Xl, Wh, Wl};
        const int rowoff[4] = {m0, m0, n0, n0};
#pragma unroll
        for (int a = 0; a < 4; a++) {
            const __nv_bfloat16* s = srcs[a];
            uint32_t ab = sb + a * ARR_B;
            cp16(ab + r0 * (SST * 2) + s0 * 16,
                 s + (size_t)(rowoff[a] + r0) * D + k0 + s0 * 8);
            cp16(ab + r1 * (SST * 2) + s1 * 16,
                 s + (size_t)(rowoff[a] + r1) * D + k0 + s1 * 8);
        }
    };

    float acc[4][4][4];
#pragma unroll
    for (int i = 0; i < 4; i++)
#pragma unroll
        for (int j = 0; j < 4; j++)
#pragma unroll
            for (int q = 0; q < 4; q++) acc[i][j][q] = 0.f;

    // ldmatrix lane addressing (byte offsets within an array)
    const int a_row_in = (lane & 7) + 8 * ((lane >> 3) & 1);
    const int a_colb = (lane >> 4) * 16;
    const int b_row_in = lane & 7;            // lanes 0-15 used by .x2
    const int b_colb = ((lane & 15) >> 3) * 16;

    stage_load(0, 0);
    CP_COMMIT();
    CP_WAIT0();
    __syncthreads();

    for (int ck = 0; ck < 32; ck++) {
        if (ck < 31) {
            stage_load((ck + 1) & 1, (ck + 1) * 32);
            CP_COMMIT();
        }
        const uint32_t sb = sbase + (uint32_t)(ck & 1) * STAGE_B;
        const uint32_t xh = sb, xl = sb + ARR_B, wh = sb + 2 * ARR_B, wl = sb + 3 * ARR_B;

#pragma unroll
        for (int ks = 0; ks < 2; ks++) {
            const int kb = ks * 32;
            uint32_t bhi[4][2], blo[4][2];
#pragma unroll
            for (int ni = 0; ni < 4; ni++) {
                uint32_t boff =
                    (uint32_t)(wn * 32 + ni * 8 + b_row_in) * (SST * 2) + kb + b_colb;
                ldsm_x2(bhi[ni][0], bhi[ni][1], wh + boff);
                ldsm_x2(blo[ni][0], blo[ni][1], wl + boff);
            }
#pragma unroll
            for (int mi = 0; mi < 4; mi++) {
                uint32_t aoff =
                    (uint32_t)(wm * 64 + mi * 16 + a_row_in) * (SST * 2) + kb + a_colb;
                uint32_t ahi[4], alo[4];
                ldsm_x4(ahi[0], ahi[1], ahi[2], ahi[3], xh + aoff);
                ldsm_x4(alo[0], alo[1], alo[2], alo[3], xl + aoff);
#pragma unroll
                for (int ni = 0; ni < 4; ni++) {
                    mma16816(acc[mi][ni], ahi, bhi[ni]);
                    mma16816(acc[mi][ni], ahi, blo[ni]);
                    mma16816(acc[mi][ni], alo, bhi[ni]);
                }
            }
        }
        CP_WAIT0();
        __syncthreads();
    }

    // ---- epilogue ----
    const int qr = lane >> 2;         // 0..7
    const int qc = (lane & 3) * 2;    // 0,2,4,6
    const int L = 1 << Lsh, Lm = L - 1;
#pragma unroll
    for (int mi = 0; mi < 4; mi++) {
#pragma unroll
        for (int rh = 0; rh < 2; rh++) {
            int m = m0 + wm * 64 + mi * 16 + qr + rh * 8;
            int bb = m >> Lsh, l = m & Lm;
#pragma unroll
            for (int ni = 0; ni < 4; ni++) {
                int n = n0 + wn * 32 + ni * 8 + qc;
                int hh = n >> 6, d0 = n & 63;
                float2 o;
                o.x = (acc[mi][ni][rh * 2 + 0] + bias[n]) * scale;
                o.y = (acc[mi][ni][rh * 2 + 1] + bias[n + 1]) * scale;
                *(float2*)(out + (((size_t)bb * H + hh) * (size_t)L + l) * DH + d0) = o;
            }
        }
    }
}

// =====================================================================
// Kernel 2: fused edge-masked attention (unchanged from R2).
// =====================================================================
#define PT 128
#define CT 64
#define QS 130
#define KS 68
#define VS 68
#define SSD 130
#define ES 68
#define OFF_K (64 * QS)
#define OFF_V (OFF_K + 64 * KS)
#define OFF_S (OFF_V + 64 * VS)
#define OFF_E (OFF_S + 64 * SSD)
#define ATTN_SMEM_FLOATS (OFF_E + 128 * ES)
#define ATTN_SMEM_BYTES (ATTN_SMEM_FLOATS * 4)

__global__ void __launch_bounds__(512) attn_kernel(
    const float* __restrict__ q, const float* __restrict__ k,
    const float* __restrict__ v, const float* __restrict__ edge,
    float* __restrict__ ctx)
{
    extern __shared__ float sm[];
    float* QsT = sm;
    float* KsT = sm + OFF_K;
    float* Vs  = sm + OFF_V;
    float* Ss  = sm + OFF_S;
    float* Es  = sm + OFF_E;

    const int tid = threadIdx.x;
    const int ty = tid >> 4, tx = tid & 15;
    const int b = blockIdx.z, h = blockIdx.y;
    const int p0 = blockIdx.x * PT;

    const float* qbase = q + (((size_t)b * H + h) * P + p0) * DH;
    const float* kbase = k + (((size_t)b * H + h) * C) * DH;
    const float* vbase = v + (((size_t)b * H + h) * C) * DH;
    const float* ebase = edge + ((size_t)b * P + p0) * C;

    for (int i = tid; i < PT * 16; i += 512) {
        int pl = i >> 4, d4 = (i & 15) << 2;
        float4 t = *(const float4*)(qbase + (size_t)pl * DH + d4);
        QsT[(d4 + 0) * QS + pl] = t.x;
        QsT[(d4 + 1) * QS + pl] = t.y;
        QsT[(d4 + 2) * QS + pl] = t.z;
        QsT[(d4 + 3) * QS + pl] = t.w;
    }

    float m_r[4] = {-3.0e38f, -3.0e38f, -3.0e38f, -3.0e38f};
    float l_r[4] = {0.f, 0.f, 0.f, 0.f};
    ull ctx2[2][4];
#pragma unroll
    for (int i = 0; i < 2; i++)
#pragma unroll
        for (int j = 0; j < 4; j++) ctx2[i][j] = 0ull;

    for (int c0 = 0; c0 < C; c0 += CT) {
        __syncthreads();

        for (int i = tid; i < CT * 16; i += 512) {
            int cl = i >> 4, d4 = (i & 15) << 2;
            float4 t = *(const float4*)(kbase + (size_t)(c0 + cl) * DH + d4);
            KsT[(d4 + 0) * KS + cl] = t.x;
            KsT[(d4 + 1) * KS + cl] = t.y;
            KsT[(d4 + 2) * KS + cl] = t.z;
            KsT[(d4 + 3) * KS + cl] = t.w;
            float4 tv = *(const float4*)(vbase + (size_t)(c0 + cl) * DH + d4);
            *(float4*)(&Vs[cl * VS + d4]) = tv;
        }
        for (int i = tid; i < PT * 16; i += 512) {
            int pl = i >> 4, c4 = (i & 15) << 2;
            *(float4*)(&Es[pl * ES + c4]) =
                *(const float4*)(ebase + (size_t)pl * C + c0 + c4);
        }
        __syncthreads();

        ull sac[2][4];
#pragma unroll
        for (int i = 0; i < 2; i++)
#pragma unroll
            for (int j = 0; j < 4; j++) sac[i][j] = 0ull;

#pragma unroll 8
        for (int d = 0; d < DH; ++d) {
            const float* qr = QsT + d * QS + ty * 4;
            ull a0 = *(const ull*)(qr);
            ull a1 = *(const ull*)(qr + 2);
            float4 bv = *(const float4*)(KsT + d * KS + tx * 4);
            ull b0 = dup2(bv.x), b1 = dup2(bv.y), b2 = dup2(bv.z), b3 = dup2(bv.w);
            ffma2(sac[0][0], a0, b0); ffma2(sac[0][1], a0, b1);
            ffma2(sac[0][2], a0, b2); ffma2(sac[0][3], a0, b3);
            ffma2(sac[1][0], a1, b0); ffma2(sac[1][1], a1, b1);
            ffma2(sac[1][2], a1, b2); ffma2(sac[1][3], a1, b3);
        }

        float vals[4][4];
#pragma unroll
        for (int j = 0; j < 4; j++) {
            float2 t0 = unpk(sac[0][j]); vals[0][j] = t0.x; vals[1][j] = t0.y;
            float2 t1 = unpk(sac[1][j]); vals[2][j] = t1.x; vals[3][j] = t1.y;
        }
        float alpha[4];
#pragma unroll
        for (int r = 0; r < 4; r++) {
            float4 ew = *(const float4*)(Es + (ty * 4 + r) * ES + tx * 4);
            float e0 = ew.x, e1 = ew.y, e2 = ew.z, e3 = ew.w;
            vals[r][0] = (e0 > 0.f) ? vals[r][0] : -1e18f;
            vals[r][1] = (e1 > 0.f) ? vals[r][1] : -1e18f;
            vals[r][2] = (e2 > 0.f) ? vals[r][2] : -1e18f;
            vals[r][3] = (e3 > 0.f) ? vals[r][3] : -1e18f;
            float mx = fmaxf(fmaxf(vals[r][0], vals[r][1]),
                             fmaxf(vals[r][2], vals[r][3]));
#pragma unroll
            for (int o = 1; o < 16; o <<= 1)
                mx = fmaxf(mx, __shfl_xor_sync(0xffffffffu, mx, o));
            float mn = fmaxf(m_r[r], mx);
            alpha[r] = __expf(m_r[r] - mn);
            m_r[r] = mn;
            float ex0 = __expf(vals[r][0] - mn);
            float ex1 = __expf(vals[r][1] - mn);
            float ex2 = __expf(vals[r][2] - mn);
            float ex3 = __expf(vals[r][3] - mn);
            float s = (ex0 + ex1) + (ex2 + ex3);
            vals[r][0] = ex0 * e0; vals[r][1] = ex1 * e1;
            vals[r][2] = ex2 * e2; vals[r][3] = ex3 * e3;
#pragma unroll
            for (int o = 1; o < 16; o <<= 1)
                s += __shfl_xor_sync(0xffffffffu, s, o);
            l_r[r] = l_r[r] * alpha[r] + s;
        }
#pragma unroll
        for (int j = 0; j < 4; j++) {
            int c = tx * 4 + j;
            *(ull*)(&Ss[c * SSD + ty * 4])     = pack2(vals[0][j], vals[1][j]);
            *(ull*)(&Ss[c * SSD + ty * 4 + 2]) = pack2(vals[2][j], vals[3][j]);
        }
        __syncthreads();

        ull al01 = pack2(alpha[0], alpha[1]);
        ull al23 = pack2(alpha[2], alpha[3]);
#pragma unroll
        for (int j = 0; j < 4; j++) {
            ctx2[0][j] = mul2(ctx2[0][j], al01);
            ctx2[1][j] = mul2(ctx2[1][j], al23);
        }
#pragma unroll 8
        for (int c = 0; c < CT; ++c) {
            const float* pr = Ss + c * SSD + ty * 4;
            ull a0 = *(const ull*)(pr);
            ull a1 = *(const ull*)(pr + 2);
            float4 vv = *(const float4*)(Vs + c * VS + tx * 4);
            ull b0 = dup2(vv.x), b1 = dup2(vv.y), b2 = dup2(vv.z), b3 = dup2(vv.w);
            ffma2(ctx2[0][0], a0, b0); ffma2(ctx2[0][1], a0, b1);
            ffma2(ctx2[0][2], a0, b2); ffma2(ctx2[0][3], a0, b3);
            ffma2(ctx2[1][0], a1, b0); ffma2(ctx2[1][1], a1, b1);
            ffma2(ctx2[1][2], a1, b2); ffma2(ctx2[1][3], a1, b3);
        }
    }

    float inv0 = 1.0f / l_r[0], inv1 = 1.0f / l_r[1];
    float inv2 = 1.0f / l_r[2], inv3 = 1.0f / l_r[3];
#pragma unroll
    for (int j = 0; j < 4; j++) {
        float2 c0v = unpk(ctx2[0][j]);
        float2 c1v = unpk(ctx2[1][j]);
        int dh = tx * 4 + j;
        size_t base = ((size_t)b * P + p0 + ty * 4) * D + h * DH + dh;
        ctx[base]                 = c0v.x * inv0;
        ctx[base + D]             = c0v.y * inv1;
        ctx[base + 2 * (size_t)D] = c1v.x * inv2;
        ctx[base + 3 * (size_t)D] = c1v.y * inv3;
    }
}

// =====================================================================
// Kernel 3: LayerNorm (unchanged).
// =====================================================================
__global__ void __launch_bounds__(256) ln_kernel(
    const float* __restrict__ x, const float* __restrict__ gamma,
    const float* __restrict__ beta, float* __restrict__ out)
{
    __shared__ float rs1[8], rs2[8];
    const int row = blockIdx.x;
    const int tid = threadIdx.x;
    const float4 xv = *(const float4*)(x + (size_t)row * D + tid * 4);
    float s1 = xv.x + xv.y + xv.z + xv.w;
    float s2 = xv.x * xv.x + xv.y * xv.y + xv.z * xv.z + xv.w * xv.w;
#pragma unroll
    for (int o = 16; o; o >>= 1) {
        s1 += __shfl_xor_sync(0xffffffffu, s1, o);
        s2 += __shfl_xor_sync(0xffffffffu, s2, o);
    }
    if ((tid & 31) == 0) { rs1[tid >> 5] = s1; rs2[tid >> 5] = s2; }
    __syncthreads();
    if (tid < 32) {
        float t1 = (tid < 8) ? rs1[tid] : 0.f;
        float t2 = (tid < 8) ? rs2[tid] : 0.f;
#pragma unroll
        for (int o = 4; o; o >>= 1) {
            t1 += __shfl_xor_sync(0xffffffffu, t1, o);
            t2 += __shfl_xor_sync(0xffffffffu, t2, o);
        }
        if (tid == 0) { rs1[0] = t1; rs2[0] = t2; }
    }
    __syncthreads();
    const float mu = rs1[0] * (1.0f / D);
    const float var = fmaxf(rs2[0] * (1.0f / D) - mu * mu, 0.f);
    const float r = rsqrtf(var + 1e-6f);
    const float4 g = *(const float4*)(gamma + tid * 4);
    const float4 bt = *(const float4*)(beta + tid * 4);
    float4 o;
    o.x = (xv.x - mu) * r * g.x + bt.x;
    o.y = (xv.y - mu) * r * g.y + bt.y;
    o.z = (xv.z - mu) * r * g.z + bt.z;
    o.w = (xv.w - mu) * r * g.w + bt.w;
    *(float4*)(out + (size_t)row * D + tid * 4) = o;
}

// =====================================================================
extern "C" void kernel_launch(void* const* d_in, const int* in_sizes, int n_in,
                              void* d_out, int out_size)
{
    const float* para    = (const float*)d_in[0];
    const float* cluster = (const float*)d_in[1];
    const float* edge    = (const float*)d_in[2];
    const float* Wq = (const float*)d_in[3];
    const float* bq = (const float*)d_in[4];
    const float* Wk = (const float*)d_in[5];
    const float* bk = (const float*)d_in[6];
    const float* Wv = (const float*)d_in[7];
    const float* bv = (const float*)d_in[8];
    const float* gamma = (const float*)d_in[9];
    const float* beta  = (const float*)d_in[10];
    float* out = (float*)d_out;

    float *qp, *kp, *vp, *cp;
    __nv_bfloat16 *pah, *pal, *clh, *cll, *wth, *wtl;
    cudaGetSymbolAddress((void**)&qp, g_q);
    cudaGetSymbolAddress((void**)&kp, g_k);
    cudaGetSymbolAddress((void**)&vp, g_v);
    cudaGetSymbolAddress((void**)&cp, g_ctx);
    cudaGetSymbolAddress((void**)&pah, g_pa_hi);
    cudaGetSymbolAddress((void**)&pal, g_pa_lo);
    cudaGetSymbolAddress((void**)&clh, g_cl_hi);
    cudaGetSymbolAddress((void**)&cll, g_cl_lo);
    cudaGetSymbolAddress((void**)&wth, g_wt_hi);
    cudaGetSymbolAddress((void**)&wtl, g_wt_lo);

    cudaFuncSetAttribute(attn_kernel,
                         cudaFuncAttributeMaxDynamicSharedMemorySize,
                         ATTN_SMEM_BYTES);
    cudaFuncSetAttribute(proj_mma,
                         cudaFuncAttributeMaxDynamicSharedMemorySize,
                         PROJ_SMEM_BYTES);

    // prep: split inputs to (hi, lo) bf16; transpose+split weights
    cvt_split<<<(B * P * D) / (256 * 4), 256>>>(para, pah, pal);
    cvt_split<<<(B * C * D) / (256 * 4), 256>>>(cluster, clh, cll);
    wt_split<<<dim3(32, 32, 3), 256>>>(Wq, Wk, Wv, wth, wtl);

    // mma.sync projections (Q, K, V in one flat launch)
    proj_mma<<<768, 256, PROJ_SMEM_BYTES>>>(pah, pal, clh, cll, wth, wtl,
                                            bq, bk, bv, qp, kp, vp);

    // fused masked attention
    attn_kernel<<<dim3(P / PT, H, B), 512, ATTN_SMEM_BYTES>>>(qp, kp, vp, edge, cp);

    // layernorm
    ln_kernel<<<B * P, 256>>>(cp, gamma, beta, out);
}

// round 5
// speedup vs baseline: 2.8372x; 1.7155x over previous
#include <cuda_runtime.h>
#include <cuda_bf16.h>
#include <math.h>
#include <stdint.h>

#define B 4
#define P 2048
#define C 512
#define D 1024
#define H 16
#define DH 64

typedef unsigned long long ull;

// ---------------- scratch (static device arrays) ----------------
__device__ __nv_bfloat16 g_qh[(size_t)B * H * P * DH];
__device__ __nv_bfloat16 g_ql[(size_t)B * H * P * DH];
__device__ __nv_bfloat16 g_kh[(size_t)B * H * C * DH];
__device__ __nv_bfloat16 g_kl[(size_t)B * H * C * DH];
__device__ __nv_bfloat16 g_vh[(size_t)B * H * C * DH];
__device__ __nv_bfloat16 g_vl[(size_t)B * H * C * DH];
__device__ float g_ctx[(size_t)B * P * D];
__device__ __nv_bfloat16 g_pa_hi[(size_t)B * P * D];
__device__ __nv_bfloat16 g_pa_lo[(size_t)B * P * D];
__device__ __nv_bfloat16 g_cl_hi[(size_t)B * C * D];
__device__ __nv_bfloat16 g_cl_lo[(size_t)B * C * D];
__device__ __nv_bfloat16 g_wt_hi[(size_t)3 * D * D];
__device__ __nv_bfloat16 g_wt_lo[(size_t)3 * D * D];

__device__ __forceinline__ uint32_t smem_u32(const void* p) {
    uint32_t a;
    asm("{ .reg .u64 t; cvta.to.shared.u64 t, %1; cvt.u32.u64 %0, t; }"
        : "=r"(a) : "l"(p));
    return a;
}

// ---------------- mma.sync helpers ----------------
__device__ __forceinline__ void ldsm_x4(uint32_t& r0, uint32_t& r1,
                                        uint32_t& r2, uint32_t& r3, uint32_t a) {
    asm volatile("ldmatrix.sync.aligned.m8n8.x4.shared.b16 {%0,%1,%2,%3}, [%4];"
                 : "=r"(r0), "=r"(r1), "=r"(r2), "=r"(r3) : "r"(a));
}
__device__ __forceinline__ void ldsm_x2(uint32_t& r0, uint32_t& r1, uint32_t a) {
    asm volatile("ldmatrix.sync.aligned.m8n8.x2.shared.b16 {%0,%1}, [%2];"
                 : "=r"(r0), "=r"(r1) : "r"(a));
}
__device__ __forceinline__ void mma16816(float* d, const uint32_t* a,
                                         const uint32_t* b) {
    asm volatile(
        "mma.sync.aligned.m16n8k16.row.col.f32.bf16.bf16.f32 "
        "{%0,%1,%2,%3}, {%4,%5,%6,%7}, {%8,%9}, {%0,%1,%2,%3};"
        : "+f"(d[0]), "+f"(d[1]), "+f"(d[2]), "+f"(d[3])
        : "r"(a[0]), "r"(a[1]), "r"(a[2]), "r"(a[3]), "r"(b[0]), "r"(b[1]));
}
__device__ __forceinline__ void cp16(uint32_t dst, const void* src) {
    asm volatile("cp.async.cg.shared.global [%0], [%1], 16;"
                 :: "r"(dst), "l"(src));
}
#define CP_COMMIT() asm volatile("cp.async.commit_group;" ::: "memory")
#define CP_WAIT0()  asm volatile("cp.async.wait_group 0;" ::: "memory")

// pack two f32 -> bf16x2 (lo in low half)
__device__ __forceinline__ uint32_t pkbf(float lo, float hi) {
    uint32_t d;
    asm("cvt.rn.bf16x2.f32 %0, %1, %2;" : "=r"(d) : "f"(hi), "f"(lo));
    return d;
}

// =====================================================================
// Prep: split fp32 -> (hi, lo) bf16.
// =====================================================================
__global__ void __launch_bounds__(256) cvt_split(
    const float* __restrict__ x, __nv_bfloat16* __restrict__ hi,
    __nv_bfloat16* __restrict__ lo)
{
    size_t i = ((size_t)blockIdx.x * 256 + threadIdx.x) * 4;
    float4 v = *(const float4*)(x + i);
    __nv_bfloat16 h0 = __float2bfloat16(v.x);
    __nv_bfloat16 h1 = __float2bfloat16(v.y);
    __nv_bfloat16 h2 = __float2bfloat16(v.z);
    __nv_bfloat16 h3 = __float2bfloat16(v.w);
    __nv_bfloat162 hp0{h0, h1}, hp1{h2, h3};
    __nv_bfloat162 lp0{__float2bfloat16(v.x - __bfloat162float(h0)),
                       __float2bfloat16(v.y - __bfloat162float(h1))};
    __nv_bfloat162 lp1{__float2bfloat16(v.z - __bfloat162float(h2)),
                       __float2bfloat16(v.w - __bfloat162float(h3))};
    *(__nv_bfloat162*)(hi + i) = hp0;
    *(__nv_bfloat162*)(hi + i + 2) = hp1;
    *(__nv_bfloat162*)(lo + i) = lp0;
    *(__nv_bfloat162*)(lo + i + 2) = lp1;
}

// =====================================================================
// Prep: transpose W [K,N] -> Wt [N,K], split hi/lo bf16.
// =====================================================================
__global__ void __launch_bounds__(256) wt_split(
    const float* __restrict__ Wq, const float* __restrict__ Wk,
    const float* __restrict__ Wv, __nv_bfloat16* __restrict__ hi,
    __nv_bfloat16* __restrict__ lo)
{
    __shared__ float t[32][33];
    const float* W = (blockIdx.z == 0) ? Wq : (blockIdx.z == 1) ? Wk : Wv;
    size_t ooff = (size_t)blockIdx.z * D * D;
    int k0 = blockIdx.x * 32, n0 = blockIdx.y * 32;
    int tx = threadIdx.x & 31, ty = threadIdx.x >> 5;
#pragma unroll
    for (int j = 0; j < 4; j++)
        t[ty + j * 8][tx] = W[(size_t)(k0 + ty + j * 8) * D + n0 + tx];
    __syncthreads();
#pragma unroll
    for (int j = 0; j < 4; j++) {
        int n = n0 + ty + j * 8, kk = k0 + tx;
        float v = t[tx][ty + j * 8];
        __nv_bfloat16 h = __float2bfloat16(v);
        hi[ooff + (size_t)n * D + kk] = h;
        lo[ooff + (size_t)n * D + kk] = __float2bfloat16(v - __bfloat162float(h));
    }
}

// =====================================================================
// Projection GEMM via mma.sync split-bf16; epilogue emits bf16 hi/lo
// in head layout [b,h,l,dh].
// =====================================================================
#define SST 40
#define ARR_B (128 * SST * 2)
#define STAGE_B (4 * ARR_B)
#define PROJ_SMEM_BYTES (2 * STAGE_B)

__global__ void __launch_bounds__(256, 2) proj_mma(
    const __nv_bfloat16* __restrict__ pa_hi, const __nv_bfloat16* __restrict__ pa_lo,
    const __nv_bfloat16* __restrict__ cl_hi, const __nv_bfloat16* __restrict__ cl_lo,
    const __nv_bfloat16* __restrict__ wt_hi, const __nv_bfloat16* __restrict__ wt_lo,
    const float* __restrict__ bq, const float* __restrict__ bk,
    const float* __restrict__ bv,
    __nv_bfloat16* __restrict__ qh, __nv_bfloat16* __restrict__ ql,
    __nv_bfloat16* __restrict__ kh, __nv_bfloat16* __restrict__ kl,
    __nv_bfloat16* __restrict__ vh, __nv_bfloat16* __restrict__ vl)
{
    extern __shared__ char smem[];
    const uint32_t sbase = smem_u32(smem);
    const int tid = threadIdx.x;
    const int wid = tid >> 5, lane = tid & 31;

    const int bid = blockIdx.x;
    const __nv_bfloat16 *Xh, *Xl, *Wh, *Wl;
    const float* bias;
    __nv_bfloat16 *oh, *ol;
    int mblk, Lsh; float scale;
    if (bid < 512) {
        Xh = pa_hi; Xl = pa_lo; Wh = wt_hi; Wl = wt_lo;
        bias = bq; oh = qh; ol = ql; Lsh = 11; scale = 0.125f; mblk = bid >> 3;
    } else if (bid < 640) {
        Xh = cl_hi; Xl = cl_lo; Wh = wt_hi + (size_t)D * D; Wl = wt_lo + (size_t)D * D;
        bias = bk; oh = kh; ol = kl; Lsh = 9; scale = 1.0f; mblk = (bid - 512) >> 3;
    } else {
        Xh = cl_hi; Xl = cl_lo; Wh = wt_hi + (size_t)2 * D * D; Wl = wt_lo + (size_t)2 * D * D;
        bias = bv; oh = vh; ol = vl; Lsh = 9; scale = 1.0f; mblk = (bid - 640) >> 3;
    }
    const int n0 = (bid & 7) * 128;
    const int m0 = mblk * 128;

    const int wm = wid >> 2, wn = wid & 3;
    const int r0l = tid >> 2, s0l = (tid & 3);
    const int r1l = (tid + 256) >> 2, s1l = ((tid + 256) & 3);

    auto stage_load = [&](int stg, int k0) {
        const uint32_t sb = sbase + (uint32_t)stg * STAGE_B;
        const __nv_bfloat16* srcs[4] = {Xh, Xl, Wh, Wl};
        const int rowoff[4] = {m0, m0, n0, n0};
#pragma unroll
        for (int a = 0; a < 4; a++) {
            const __nv_bfloat16* s = srcs[a];
            uint32_t ab = sb + a * ARR_B;
            cp16(ab + r0l * (SST * 2) + s0l * 16,
                 s + (size_t)(rowoff[a] + r0l) * D + k0 + s0l * 8);
            cp16(ab + r1l * (SST * 2) + s1l * 16,
                 s + (size_t)(rowoff[a] + r1l) * D + k0 + s1l * 8);
        }
    };

    float acc[4][4][4];
#pragma unroll
    for (int i = 0; i < 4; i++)
#pragma unroll
        for (int j = 0; j < 4; j++)
#pragma unroll
            for (int q = 0; q < 4; q++) acc[i][j][q] = 0.f;

    const int a_row_in = (lane & 7) + 8 * ((lane >> 3) & 1);
    const int a_colb = (lane >> 4) * 16;
    const int b_row_in = lane & 7;
    const int b_colb = ((lane & 15) >> 3) * 16;

    stage_load(0, 0);
    CP_COMMIT();
    CP_WAIT0();
    __syncthreads();

    for (int ck = 0; ck < 32; ck++) {
        if (ck < 31) {
            stage_load((ck + 1) & 1, (ck + 1) * 32);
            CP_COMMIT();
        }
        const uint32_t sb = sbase + (uint32_t)(ck & 1) * STAGE_B;
        const uint32_t xh = sb, xl = sb + ARR_B, wh = sb + 2 * ARR_B, wl = sb + 3 * ARR_B;

#pragma unroll
        for (int ks = 0; ks < 2; ks++) {
            const int kb = ks * 32;
            uint32_t bhi[4][2], blo[4][2];
#pragma unroll
            for (int ni = 0; ni < 4; ni++) {
                uint32_t boff =
                    (uint32_t)(wn * 32 + ni * 8 + b_row_in) * (SST * 2) + kb + b_colb;
                ldsm_x2(bhi[ni][0], bhi[ni][1], wh + boff);
                ldsm_x2(blo[ni][0], blo[ni][1], wl + boff);
            }
#pragma unroll
            for (int mi = 0; mi < 4; mi++) {
                uint32_t aoff =
                    (uint32_t)(wm * 64 + mi * 16 + a_row_in) * (SST * 2) + kb + a_colb;
                uint32_t ahi[4], alo[4];
                ldsm_x4(ahi[0], ahi[1], ahi[2], ahi[3], xh + aoff);
                ldsm_x4(alo[0], alo[1], alo[2], alo[3], xl + aoff);
#pragma unroll
                for (int ni = 0; ni < 4; ni++) {
                    mma16816(acc[mi][ni], ahi, bhi[ni]);
                    mma16816(acc[mi][ni], ahi, blo[ni]);
                    mma16816(acc[mi][ni], alo, bhi[ni]);
                }
            }
        }
        CP_WAIT0();
        __syncthreads();
    }

    // epilogue: split to bf16 hi/lo, head layout
    const int qr = lane >> 2;
    const int qc = (lane & 3) * 2;
    const int L = 1 << Lsh, Lm = L - 1;
#pragma unroll
    for (int mi = 0; mi < 4; mi++) {
#pragma unroll
        for (int rh = 0; rh < 2; rh++) {
            int m = m0 + wm * 64 + mi * 16 + qr + rh * 8;
            int bb = m >> Lsh, l = m & Lm;
#pragma unroll
            for (int ni = 0; ni < 4; ni++) {
                int n = n0 + wn * 32 + ni * 8 + qc;
                int hh = n >> 6, d0 = n & 63;
                float ox = (acc[mi][ni][rh * 2 + 0] + bias[n]) * scale;
                float oy = (acc[mi][ni][rh * 2 + 1] + bias[n + 1]) * scale;
                uint32_t hp = pkbf(ox, oy);
                float hx = __uint_as_float(hp << 16);
                float hy = __uint_as_float(hp & 0xffff0000u);
                uint32_t lp = pkbf(ox - hx, oy - hy);
                size_t off = (((size_t)bb * H + hh) * (size_t)L + l) * DH + d0;
                *(uint32_t*)(oh + off) = hp;
                *(uint32_t*)(ol + off) = lp;
            }
        }
    }
}

// =====================================================================
// Fused edge-masked attention, mma.sync split-bf16, online softmax
// in fragment registers.  Block: 256 thr = 8 warps x 16 p-rows = 128.
// C chunks of 64.
// =====================================================================
#define ASTRIDE 144                      // bytes per smem row (72 bf16)
#define OFF_QH 0
#define OFF_QL 18432
#define OFF_KH 36864
#define OFF_KL 46080
#define OFF_VH 55296
#define OFF_VL 64512
#define ATTN_SMEM_BYTES 73728

__global__ void __launch_bounds__(256, 2) attn_mma(
    const __nv_bfloat16* __restrict__ qh, const __nv_bfloat16* __restrict__ ql,
    const __nv_bfloat16* __restrict__ kh, const __nv_bfloat16* __restrict__ kl,
    const __nv_bfloat16* __restrict__ vh, const __nv_bfloat16* __restrict__ vl,
    const float* __restrict__ edge, float* __restrict__ ctx)
{
    extern __shared__ char smem[];
    const uint32_t sbase = smem_u32(smem);
    const int tid = threadIdx.x;
    const int wid = tid >> 5, lane = tid & 31;
    const int b = blockIdx.z, h = blockIdx.y;
    const int p0 = blockIdx.x * 128;

    const size_t qoff = (((size_t)b * H + h) * P + p0) * DH;
    const size_t koff = (((size_t)b * H + h) * C) * DH;
    const float* ebase = edge + ((size_t)b * P + p0) * C;

    // Q tile -> smem (cp.async), persists across chunks
#pragma unroll
    for (int i = 0; i < 8; i++) {
        int g = tid + i * 256;
        int arr = g >> 10, rem = g & 1023;
        int row = rem >> 3, seg = rem & 7;
        const __nv_bfloat16* src = (arr ? ql : qh) + qoff + (size_t)row * DH + seg * 8;
        cp16(sbase + arr * 18432 + row * ASTRIDE + seg * 16, src);
    }
    CP_COMMIT();

    const int a_row = (lane & 7) + 8 * ((lane >> 3) & 1);
    const int a_colb = (lane >> 4) * 16;
    const int b_row = lane & 7;
    const int b_colb = ((lane & 15) >> 3) * 16;
    const int r0 = lane >> 2;           // row within warp band
    const int wr = wid * 16;            // warp row base
    const int c2 = (lane & 3) * 2;      // col pair within 8-tile

    float m_r[2] = {-3.0e38f, -3.0e38f};
    float l_r[2] = {0.f, 0.f};
    float cacc[8][4];
#pragma unroll
    for (int i = 0; i < 8; i++)
#pragma unroll
        for (int j = 0; j < 4; j++) cacc[i][j] = 0.f;

    for (int ck = 0; ck < 8; ck++) {
        const int c0 = ck * 64;
        __syncthreads();   // previous chunk's reads done

        // K chunk via cp.async
#pragma unroll
        for (int i = 0; i < 4; i++) {
            int g = tid + i * 256;
            int arr = g >> 9, rem = g & 511;
            int row = rem >> 3, seg = rem & 7;
            const __nv_bfloat16* src =
                (arr ? kl : kh) + koff + (size_t)(c0 + row) * DH + seg * 8;
            cp16(sbase + OFF_KH + arr * 9216 + row * ASTRIDE + seg * 16, src);
        }
        CP_COMMIT();

        // V chunk transposed into smem: Vt[dh][c]
#pragma unroll
        for (int i = 0; i < 16; i++) {
            int g = tid + i * 256;
            int arr = g >> 11, rem = g & 2047;
            int c = rem >> 5, dp = rem & 31;
            const __nv_bfloat16* vsrc =
                (arr ? vl : vh) + koff + (size_t)(c0 + c) * DH + dp * 2;
            uint32_t val = *(const uint32_t*)vsrc;
            uint16_t* vt = (uint16_t*)(smem + (arr ? OFF_VL : OFF_VH));
            vt[(dp * 2) * 72 + c] = (uint16_t)(val & 0xffff);
            vt[(dp * 2 + 1) * 72 + c] = (uint16_t)(val >> 16);
        }
        CP_WAIT0();
        __syncthreads();

        // ---- S = Q K^T (3-pass split) ----
        float s[8][4];
#pragma unroll
        for (int i = 0; i < 8; i++)
#pragma unroll
            for (int j = 0; j < 4; j++) s[i][j] = 0.f;

#pragma unroll
        for (int ks = 0; ks < 4; ks++) {
            uint32_t aoff = (uint32_t)(wr + a_row) * ASTRIDE + a_colb + ks * 32;
            uint32_t ah[4], al[4];
            ldsm_x4(ah[0], ah[1], ah[2], ah[3], sbase + OFF_QH + aoff);
            ldsm_x4(al[0], al[1], al[2], al[3], sbase + OFF_QL + aoff);
#pragma unroll
            for (int ni = 0; ni < 8; ni++) {
                uint32_t boff = (uint32_t)(ni * 8 + b_row) * ASTRIDE + b_colb + ks * 32;
                uint32_t bh[2], bl[2];
                ldsm_x2(bh[0], bh[1], sbase + OFF_KH + boff);
                ldsm_x2(bl[0], bl[1], sbase + OFF_KL + boff);
                mma16816(s[ni], ah, bh);
                mma16816(s[ni], al, bh);
                mma16816(s[ni], ah, bl);
            }
        }

        // ---- online softmax on fragments ----
        float alpha[2];
#pragma unroll
        for (int rr = 0; rr < 2; rr++) {
            const int row = wr + r0 + rr * 8;
            const float* erow = ebase + (size_t)row * C + c0 + c2;
            float ev[8][2];
            float mx = -3.0e38f;
#pragma unroll
            for (int j = 0; j < 8; j++) {
                float2 e2 = *(const float2*)(erow + j * 8);
                ev[j][0] = e2.x; ev[j][1] = e2.y;
                float s0 = (e2.x > 0.f) ? s[j][rr * 2] : -1e18f;
                float s1 = (e2.y > 0.f) ? s[j][rr * 2 + 1] : -1e18f;
                s[j][rr * 2] = s0; s[j][rr * 2 + 1] = s1;
                mx = fmaxf(mx, fmaxf(s0, s1));
            }
            mx = fmaxf(mx, __shfl_xor_sync(0xffffffffu, mx, 1));
            mx = fmaxf(mx, __shfl_xor_sync(0xffffffffu, mx, 2));
            float mn = fmaxf(m_r[rr], mx);
            alpha[rr] = __expf(m_r[rr] - mn);
            m_r[rr] = mn;
            float ls = 0.f;
#pragma unroll
            for (int j = 0; j < 8; j++) {
                float ex0 = __expf(s[j][rr * 2] - mn);
                float ex1 = __expf(s[j][rr * 2 + 1] - mn);
                ls += ex0 + ex1;
                s[j][rr * 2] = ex0 * ev[j][0];
                s[j][rr * 2 + 1] = ex1 * ev[j][1];
            }
            ls += __shfl_xor_sync(0xffffffffu, ls, 1);
            ls += __shfl_xor_sync(0xffffffffu, ls, 2);
            l_r[rr] = l_r[rr] * alpha[rr] + ls;
        }

        // ---- rescale ctx, then ctx += P V (3-pass split) ----
#pragma unroll
        for (int ni = 0; ni < 8; ni++) {
            cacc[ni][0] *= alpha[0]; cacc[ni][1] *= alpha[0];
            cacc[ni][2] *= alpha[1]; cacc[ni][3] *= alpha[1];
        }
#pragma unroll
        for (int ks = 0; ks < 4; ks++) {
            const float* t0 = s[2 * ks];
            const float* t1 = s[2 * ks + 1];
            uint32_t ah[4], al[4];
#pragma unroll
            for (int q = 0; q < 4; q++) {
                const float* tt = (q < 2) ? t0 : t1;
                float v0 = tt[(q & 1) * 2], v1 = tt[(q & 1) * 2 + 1];
                uint32_t hp = pkbf(v0, v1);
                float h0 = __uint_as_float(hp << 16);
                float h1 = __uint_as_float(hp & 0xffff0000u);
                ah[q] = hp;
                al[q] = pkbf(v0 - h0, v1 - h1);
            }
#pragma unroll
            for (int ni = 0; ni < 8; ni++) {
                uint32_t boff = (uint32_t)(ni * 8 + b_row) * ASTRIDE + b_colb + ks * 32;
                uint32_t bh[2], bl[2];
                ldsm_x2(bh[0], bh[1], sbase + OFF_VH + boff);
                ldsm_x2(bl[0], bl[1], sbase + OFF_VL + boff);
                mma16816(cacc[ni], ah, bh);
                mma16816(cacc[ni], al, bh);
                mma16816(cacc[ni], ah, bl);
            }
        }
    }

    // ---- finalize ----
    const float inv0 = 1.0f / l_r[0];
    const float inv1 = 1.0f / l_r[1];
    const int row0 = p0 + wr + r0;
#pragma unroll
    for (int ni = 0; ni < 8; ni++) {
        int dh = ni * 8 + c2;
        size_t base0 = ((size_t)b * P + row0) * D + h * DH + dh;
        float2 o0{cacc[ni][0] * inv0, cacc[ni][1] * inv0};
        float2 o1{cacc[ni][2] * inv1, cacc[ni][3] * inv1};
        *(float2*)(ctx + base0) = o0;
        *(float2*)(ctx + base0 + (size_t)8 * D) = o1;
    }
}

// =====================================================================
// LayerNorm over D=1024.
// =====================================================================
__global__ void __launch_bounds__(256) ln_kernel(
    const float* __restrict__ x, const float* __restrict__ gamma,
    const float* __restrict__ beta, float* __restrict__ out)
{
    __shared__ float rs1[8], rs2[8];
    const int row = blockIdx.x;
    const int tid = threadIdx.x;
    const float4 xv = *(const float4*)(x + (size_t)row * D + tid * 4);
    float s1 = xv.x + xv.y + xv.z + xv.w;
    float s2 = xv.x * xv.x + xv.y * xv.y + xv.z * xv.z + xv.w * xv.w;
#pragma unroll
    for (int o = 16; o; o >>= 1) {
        s1 += __shfl_xor_sync(0xffffffffu, s1, o);
        s2 += __shfl_xor_sync(0xffffffffu, s2, o);
    }
    if ((tid & 31) == 0) { rs1[tid >> 5] = s1; rs2[tid >> 5] = s2; }
    __syncthreads();
    if (tid < 32) {
        float t1 = (tid < 8) ? rs1[tid] : 0.f;
        float t2 = (tid < 8) ? rs2[tid] : 0.f;
#pragma unroll
        for (int o = 4; o; o >>= 1) {
            t1 += __shfl_xor_sync(0xffffffffu, t1, o);
            t2 += __shfl_xor_sync(0xffffffffu, t2, o);
        }
        if (tid == 0) { rs1[0] = t1; rs2[0] = t2; }
    }
    __syncthreads();
    const float mu = rs1[0] * (1.0f / D);
    const float var = fmaxf(rs2[0] * (1.0f / D) - mu * mu, 0.f);
    const float r = rsqrtf(var + 1e-6f);
    const float4 g = *(const float4*)(gamma + tid * 4);
    const float4 bt = *(const float4*)(beta + tid * 4);
    float4 o;
    o.x = (xv.x - mu) * r * g.x + bt.x;
    o.y = (xv.y - mu) * r * g.y + bt.y;
    o.z = (xv.z - mu) * r * g.z + bt.z;
    o.w = (xv.w - mu) * r * g.w + bt.w;
    *(float4*)(out + (size_t)row * D + tid * 4) = o;
}

// =====================================================================
extern "C" void kernel_launch(void* const* d_in, const int* in_sizes, int n_in,
                              void* d_out, int out_size)
{
    const float* para    = (const float*)d_in[0];
    const float* cluster = (const float*)d_in[1];
    const float* edge    = (const float*)d_in[2];
    const float* Wq = (const float*)d_in[3];
    const float* bq = (const float*)d_in[4];
    const float* Wk = (const float*)d_in[5];
    const float* bk = (const float*)d_in[6];
    const float* Wv = (const float*)d_in[7];
    const float* bv = (const float*)d_in[8];
    const float* gamma = (const float*)d_in[9];
    const float* beta  = (const float*)d_in[10];
    float* out = (float*)d_out;

    float* cp;
    __nv_bfloat16 *qhp, *qlp, *khp, *klp, *vhp, *vlp;
    __nv_bfloat16 *pah, *pal, *clh, *cll, *wth, *wtl;
    cudaGetSymbolAddress((void**)&cp, g_ctx);
    cudaGetSymbolAddress((void**)&qhp, g_qh);
    cudaGetSymbolAddress((void**)&qlp, g_ql);
    cudaGetSymbolAddress((void**)&khp, g_kh);
    cudaGetSymbolAddress((void**)&klp, g_kl);
    cudaGetSymbolAddress((void**)&vhp, g_vh);
    cudaGetSymbolAddress((void**)&vlp, g_vl);
    cudaGetSymbolAddress((void**)&pah, g_pa_hi);
    cudaGetSymbolAddress((void**)&pal, g_pa_lo);
    cudaGetSymbolAddress((void**)&clh, g_cl_hi);
    cudaGetSymbolAddress((void**)&cll, g_cl_lo);
    cudaGetSymbolAddress((void**)&wth, g_wt_hi);
    cudaGetSymbolAddress((void**)&wtl, g_wt_lo);

    cudaFuncSetAttribute(proj_mma,
                         cudaFuncAttributeMaxDynamicSharedMemorySize,
                         PROJ_SMEM_BYTES);
    cudaFuncSetAttribute(attn_mma,
                         cudaFuncAttributeMaxDynamicSharedMemorySize,
                         ATTN_SMEM_BYTES);

    cvt_split<<<(B * P * D) / (256 * 4), 256>>>(para, pah, pal);
    cvt_split<<<(B * C * D) / (256 * 4), 256>>>(cluster, clh, cll);
    wt_split<<<dim3(32, 32, 3), 256>>>(Wq, Wk, Wv, wth, wtl);

    proj_mma<<<768, 256, PROJ_SMEM_BYTES>>>(pah, pal, clh, cll, wth, wtl,
                                            bq, bk, bv,
                                            qhp, qlp, khp, klp, vhp, vlp);

    attn_mma<<<dim3(P / 128, H, B), 256, ATTN_SMEM_BYTES>>>(
        qhp, qlp, khp, klp, vhp, vlp, edge, cp);

    ln_kernel<<<B * P, 256>>>(cp, gamma, beta, out);
}

// round 6
// speedup vs baseline: 3.1992x; 1.1276x over previous
#include <cuda_runtime.h>
#include <cuda_bf16.h>
#include <math.h>
#include <stdint.h>

#define B 4
#define P 2048
#define C 512
#define D 1024
#define H 16
#define DH 64

// ---------------- scratch (static device arrays) ----------------
__device__ __nv_bfloat16 g_qh[(size_t)B * H * P * DH];
__device__ __nv_bfloat16 g_ql[(size_t)B * H * P * DH];
__device__ __nv_bfloat16 g_kh[(size_t)B * H * C * DH];
__device__ __nv_bfloat16 g_kl[(size_t)B * H * C * DH];
__device__ __nv_bfloat16 g_vh[(size_t)B * H * C * DH];
__device__ __nv_bfloat16 g_vl[(size_t)B * H * C * DH];
__device__ float g_ctx[(size_t)B * P * D];
__device__ __nv_bfloat16 g_pa_hi[(size_t)B * P * D];
__device__ __nv_bfloat16 g_pa_lo[(size_t)B * P * D];
__device__ __nv_bfloat16 g_cl_hi[(size_t)B * C * D];
__device__ __nv_bfloat16 g_cl_lo[(size_t)B * C * D];
__device__ __nv_bfloat16 g_wt_hi[(size_t)3 * D * D];
__device__ __nv_bfloat16 g_wt_lo[(size_t)3 * D * D];

__device__ __forceinline__ uint32_t smem_u32(const void* p) {
    uint32_t a;
    asm("{ .reg .u64 t; cvta.to.shared.u64 t, %1; cvt.u32.u64 %0, t; }"
        : "=r"(a) : "l"(p));
    return a;
}

// ---------------- mma.sync helpers ----------------
__device__ __forceinline__ void ldsm_x4(uint32_t& r0, uint32_t& r1,
                                        uint32_t& r2, uint32_t& r3, uint32_t a) {
    asm volatile("ldmatrix.sync.aligned.m8n8.x4.shared.b16 {%0,%1,%2,%3}, [%4];"
                 : "=r"(r0), "=r"(r1), "=r"(r2), "=r"(r3) : "r"(a));
}
__device__ __forceinline__ void ldsm_x2(uint32_t& r0, uint32_t& r1, uint32_t a) {
    asm volatile("ldmatrix.sync.aligned.m8n8.x2.shared.b16 {%0,%1}, [%2];"
                 : "=r"(r0), "=r"(r1) : "r"(a));
}
__device__ __forceinline__ void ldsm_x2t(uint32_t& r0, uint32_t& r1, uint32_t a) {
    asm volatile("ldmatrix.sync.aligned.m8n8.x2.trans.shared.b16 {%0,%1}, [%2];"
                 : "=r"(r0), "=r"(r1) : "r"(a));
}
__device__ __forceinline__ void mma16816(float* d, const uint32_t* a,
                                         const uint32_t* b) {
    asm volatile(
        "mma.sync.aligned.m16n8k16.row.col.f32.bf16.bf16.f32 "
        "{%0,%1,%2,%3}, {%4,%5,%6,%7}, {%8,%9}, {%0,%1,%2,%3};"
        : "+f"(d[0]), "+f"(d[1]), "+f"(d[2]), "+f"(d[3])
        : "r"(a[0]), "r"(a[1]), "r"(a[2]), "r"(a[3]), "r"(b[0]), "r"(b[1]));
}
__device__ __forceinline__ void cp16(uint32_t dst, const void* src) {
    asm volatile("cp.async.cg.shared.global [%0], [%1], 16;"
                 :: "r"(dst), "l"(src));
}
#define CP_COMMIT() asm volatile("cp.async.commit_group;" ::: "memory")
#define CP_WAIT0()  asm volatile("cp.async.wait_group 0;" ::: "memory")

__device__ __forceinline__ uint32_t pkbf(float lo, float hi) {
    uint32_t d;
    asm("cvt.rn.bf16x2.f32 %0, %1, %2;" : "=r"(d) : "f"(hi), "f"(lo));
    return d;
}
__device__ __forceinline__ float exp2r(float x) {
    float y; asm("ex2.approx.ftz.f32 %0, %1;" : "=f"(y) : "f"(x)); return y;
}

// =====================================================================
// Prep: split fp32 -> (hi, lo) bf16.
// =====================================================================
__global__ void __launch_bounds__(256) cvt_split(
    const float* __restrict__ x, __nv_bfloat16* __restrict__ hi,
    __nv_bfloat16* __restrict__ lo)
{
    size_t i = ((size_t)blockIdx.x * 256 + threadIdx.x) * 4;
    float4 v = *(const float4*)(x + i);
    __nv_bfloat16 h0 = __float2bfloat16(v.x);
    __nv_bfloat16 h1 = __float2bfloat16(v.y);
    __nv_bfloat16 h2 = __float2bfloat16(v.z);
    __nv_bfloat16 h3 = __float2bfloat16(v.w);
    __nv_bfloat162 hp0{h0, h1}, hp1{h2, h3};
    __nv_bfloat162 lp0{__float2bfloat16(v.x - __bfloat162float(h0)),
                       __float2bfloat16(v.y - __bfloat162float(h1))};
    __nv_bfloat162 lp1{__float2bfloat16(v.z - __bfloat162float(h2)),
                       __float2bfloat16(v.w - __bfloat162float(h3))};
    *(__nv_bfloat162*)(hi + i) = hp0;
    *(__nv_bfloat162*)(hi + i + 2) = hp1;
    *(__nv_bfloat162*)(lo + i) = lp0;
    *(__nv_bfloat162*)(lo + i + 2) = lp1;
}

// =====================================================================
// Prep: transpose W [K,N] -> Wt [N,K], split hi/lo bf16.
// =====================================================================
__global__ void __launch_bounds__(256) wt_split(
    const float* __restrict__ Wq, const float* __restrict__ Wk,
    const float* __restrict__ Wv, __nv_bfloat16* __restrict__ hi,
    __nv_bfloat16* __restrict__ lo)
{
    __shared__ float t[32][33];
    const float* W = (blockIdx.z == 0) ? Wq : (blockIdx.z == 1) ? Wk : Wv;
    size_t ooff = (size_t)blockIdx.z * D * D;
    int k0 = blockIdx.x * 32, n0 = blockIdx.y * 32;
    int tx = threadIdx.x & 31, ty = threadIdx.x >> 5;
#pragma unroll
    for (int j = 0; j < 4; j++)
        t[ty + j * 8][tx] = W[(size_t)(k0 + ty + j * 8) * D + n0 + tx];
    __syncthreads();
#pragma unroll
    for (int j = 0; j < 4; j++) {
        int n = n0 + ty + j * 8, kk = k0 + tx;
        float v = t[tx][ty + j * 8];
        __nv_bfloat16 h = __float2bfloat16(v);
        hi[ooff + (size_t)n * D + kk] = h;
        lo[ooff + (size_t)n * D + kk] = __float2bfloat16(v - __bfloat162float(h));
    }
}

// =====================================================================
// Projection GEMM via mma.sync split-bf16 (unchanged except Q scale
// now folds log2(e) so attention works in exp2 domain).
// =====================================================================
#define SST 40
#define ARR_B (128 * SST * 2)
#define STAGE_B (4 * ARR_B)
#define PROJ_SMEM_BYTES (2 * STAGE_B)

__global__ void __launch_bounds__(256, 2) proj_mma(
    const __nv_bfloat16* __restrict__ pa_hi, const __nv_bfloat16* __restrict__ pa_lo,
    const __nv_bfloat16* __restrict__ cl_hi, const __nv_bfloat16* __restrict__ cl_lo,
    const __nv_bfloat16* __restrict__ wt_hi, const __nv_bfloat16* __restrict__ wt_lo,
    const float* __restrict__ bq, const float* __restrict__ bk,
    const float* __restrict__ bv,
    __nv_bfloat16* __restrict__ qh, __nv_bfloat16* __restrict__ ql,
    __nv_bfloat16* __restrict__ kh, __nv_bfloat16* __restrict__ kl,
    __nv_bfloat16* __restrict__ vh, __nv_bfloat16* __restrict__ vl)
{
    extern __shared__ char smem[];
    const uint32_t sbase = smem_u32(smem);
    const int tid = threadIdx.x;
    const int wid = tid >> 5, lane = tid & 31;

    const int bid = blockIdx.x;
    const __nv_bfloat16 *Xh, *Xl, *Wh, *Wl;
    const float* bias;
    __nv_bfloat16 *oh, *ol;
    int mblk, Lsh; float scale;
    if (bid < 512) {
        Xh = pa_hi; Xl = pa_lo; Wh = wt_hi; Wl = wt_lo;
        bias = bq; oh = qh; ol = ql; Lsh = 11;
        scale = 0.125f * 1.44269504f;          // 1/sqrt(DH) * log2(e)
        mblk = bid >> 3;
    } else if (bid < 640) {
        Xh = cl_hi; Xl = cl_lo; Wh = wt_hi + (size_t)D * D; Wl = wt_lo + (size_t)D * D;
        bias = bk; oh = kh; ol = kl; Lsh = 9; scale = 1.0f; mblk = (bid - 512) >> 3;
    } else {
        Xh = cl_hi; Xl = cl_lo; Wh = wt_hi + (size_t)2 * D * D; Wl = wt_lo + (size_t)2 * D * D;
        bias = bv; oh = vh; ol = vl; Lsh = 9; scale = 1.0f; mblk = (bid - 640) >> 3;
    }
    const int n0 = (bid & 7) * 128;
    const int m0 = mblk * 128;

    const int wm = wid >> 2, wn = wid & 3;
    const int r0l = tid >> 2, s0l = (tid & 3);
    const int r1l = (tid + 256) >> 2, s1l = ((tid + 256) & 3);

    auto stage_load = [&](int stg, int k0) {
        const uint32_t sb = sbase + (uint32_t)stg * STAGE_B;
        const __nv_bfloat16* srcs[4] = {Xh, Xl, Wh, Wl};
        const int rowoff[4] = {m0, m0, n0, n0};
#pragma unroll
        for (int a = 0; a < 4; a++) {
            const __nv_bfloat16* s = srcs[a];
            uint32_t ab = sb + a * ARR_B;
            cp16(ab + r0l * (SST * 2) + s0l * 16,
                 s + (size_t)(rowoff[a] + r0l) * D + k0 + s0l * 8);
            cp16(ab + r1l * (SST * 2) + s1l * 16,
                 s + (size_t)(rowoff[a] + r1l) * D + k0 + s1l * 8);
        }
    };

    float acc[4][4][4];
#pragma unroll
    for (int i = 0; i < 4; i++)
#pragma unroll
        for (int j = 0; j < 4; j++)
#pragma unroll
            for (int q = 0; q < 4; q++) acc[i][j][q] = 0.f;

    const int a_row_in = (lane & 7) + 8 * ((lane >> 3) & 1);
    const int a_colb = (lane >> 4) * 16;
    const int b_row_in = lane & 7;
    const int b_colb = ((lane & 15) >> 3) * 16;

    stage_load(0, 0);
    CP_COMMIT();
    CP_WAIT0();
    __syncthreads();

    for (int ck = 0; ck < 32; ck++) {
        if (ck < 31) {
            stage_load((ck + 1) & 1, (ck + 1) * 32);
            CP_COMMIT();
        }
        const uint32_t sb = sbase + (uint32_t)(ck & 1) * STAGE_B;
        const uint32_t xh = sb, xl = sb + ARR_B, wh = sb + 2 * ARR_B, wl = sb + 3 * ARR_B;

#pragma unroll
        for (int ks = 0; ks < 2; ks++) {
            const int kb = ks * 32;
            uint32_t bhi[4][2], blo[4][2];
#pragma unroll
            for (int ni = 0; ni < 4; ni++) {
                uint32_t boff =
                    (uint32_t)(wn * 32 + ni * 8 + b_row_in) * (SST * 2) + kb + b_colb;
                ldsm_x2(bhi[ni][0], bhi[ni][1], wh + boff);
                ldsm_x2(blo[ni][0], blo[ni][1], wl + boff);
            }
#pragma unroll
            for (int mi = 0; mi < 4; mi++) {
                uint32_t aoff =
                    (uint32_t)(wm * 64 + mi * 16 + a_row_in) * (SST * 2) + kb + a_colb;
                uint32_t ahi[4], alo[4];
                ldsm_x4(ahi[0], ahi[1], ahi[2], ahi[3], xh + aoff);
                ldsm_x4(alo[0], alo[1], alo[2], alo[3], xl + aoff);
#pragma unroll
                for (int ni = 0; ni < 4; ni++) {
                    mma16816(acc[mi][ni], ahi, bhi[ni]);
                    mma16816(acc[mi][ni], ahi, blo[ni]);
                    mma16816(acc[mi][ni], alo, bhi[ni]);
                }
            }
        }
        CP_WAIT0();
        __syncthreads();
    }

    const int qr = lane >> 2;
    const int qc = (lane & 3) * 2;
    const int L = 1 << Lsh, Lm = L - 1;
#pragma unroll
    for (int mi = 0; mi < 4; mi++) {
#pragma unroll
        for (int rh = 0; rh < 2; rh++) {
            int m = m0 + wm * 64 + mi * 16 + qr + rh * 8;
            int bb = m >> Lsh, l = m & Lm;
#pragma unroll
            for (int ni = 0; ni < 4; ni++) {
                int n = n0 + wn * 32 + ni * 8 + qc;
                int hh = n >> 6, d0 = n & 63;
                float ox = (acc[mi][ni][rh * 2 + 0] + bias[n]) * scale;
                float oy = (acc[mi][ni][rh * 2 + 1] + bias[n + 1]) * scale;
                uint32_t hp = pkbf(ox, oy);
                float hx = __uint_as_float(hp << 16);
                float hy = __uint_as_float(hp & 0xffff0000u);
                uint32_t lp = pkbf(ox - hx, oy - hy);
                size_t off = (((size_t)bb * H + hh) * (size_t)L + l) * DH + d0;
                *(uint32_t*)(oh + off) = hp;
                *(uint32_t*)(ol + off) = lp;
            }
        }
    }
}

// =====================================================================
// Fused attention: CT=32 double-buffered cp.async pipeline (K,V,E),
// V via ldmatrix.trans, Q fragments register-resident, exp2 softmax.
// =====================================================================
#define AST 144
#define STG0 36864
#define STG_SZ 36864
// stage interior: KH 0, KL 4608, VH 9216, VL 13824, E 18432 (f32, 144B rows)
#define ATTN_SMEM_BYTES (STG0 + 2 * STG_SZ)

__global__ void __launch_bounds__(256, 2) attn_mma(
    const __nv_bfloat16* __restrict__ qh, const __nv_bfloat16* __restrict__ ql,
    const __nv_bfloat16* __restrict__ kh, const __nv_bfloat16* __restrict__ kl,
    const __nv_bfloat16* __restrict__ vh, const __nv_bfloat16* __restrict__ vl,
    const float* __restrict__ edge, float* __restrict__ ctx)
{
    extern __shared__ char smem[];
    const uint32_t sbase = smem_u32(smem);
    const int tid = threadIdx.x;
    const int wid = tid >> 5, lane = tid & 31;
    const int b = blockIdx.z, h = blockIdx.y;
    const int p0 = blockIdx.x * 128;

    const size_t qoff = (((size_t)b * H + h) * P + p0) * DH;
    const size_t koff = (((size_t)b * H + h) * C) * DH;
    const float* ebase = edge + ((size_t)b * P + p0) * C;

    const int krow = tid >> 3, kseg = tid & 7;
    const __nv_bfloat16* kvarr[4] = {kh, kl, vh, vl};

    auto load_chunk = [&](uint32_t stg, int cn) {
#pragma unroll
        for (int q = 0; q < 4; q++)
            cp16(stg + q * 4608 + krow * AST + kseg * 16,
                 kvarr[q] + koff + (size_t)(cn + krow) * DH + kseg * 8);
#pragma unroll
        for (int i = 0; i < 4; i++) {
            int er = (tid + i * 256) >> 3;
            cp16(stg + 18432 + er * AST + kseg * 16,
                 ebase + (size_t)er * C + cn + kseg * 4);
        }
    };

    // prologue: Q tile + chunk 0
#pragma unroll
    for (int i = 0; i < 8; i++) {
        int g = tid + i * 256;
        int arr = g >> 10, rem = g & 1023;
        int row = rem >> 3, seg = rem & 7;
        cp16(sbase + arr * 18432 + row * AST + seg * 16,
             (arr ? ql : qh) + qoff + (size_t)row * DH + seg * 8);
    }
    load_chunk(sbase + STG0, 0);
    CP_COMMIT();

    const int a_row = (lane & 7) + 8 * ((lane >> 3) & 1);
    const int a_colb = (lane >> 4) * 16;
    const int b_row = lane & 7;
    const int b_colb = ((lane & 15) >> 3) * 16;
    const int r0 = lane >> 2;
    const int wr = wid * 16;
    const int c2 = (lane & 3) * 2;

    CP_WAIT0();
    __syncthreads();

    // Q fragments, register-resident for all chunks
    uint32_t qfh[4][4], qfl[4][4];
#pragma unroll
    for (int ks = 0; ks < 4; ks++) {
        uint32_t aoff = (uint32_t)(wr + a_row) * AST + a_colb + ks * 32;
        ldsm_x4(qfh[ks][0], qfh[ks][1], qfh[ks][2], qfh[ks][3], sbase + aoff);
        ldsm_x4(qfl[ks][0], qfl[ks][1], qfl[ks][2], qfl[ks][3],
                sbase + 18432 + aoff);
    }

    float m_r[2] = {-1e30f, -1e30f};
    float l_r[2] = {0.f, 0.f};
    float cacc[8][4];
#pragma unroll
    for (int i = 0; i < 8; i++)
#pragma unroll
        for (int j = 0; j < 4; j++) cacc[i][j] = 0.f;

    for (int ck = 0; ck < 16; ck++) {
        const uint32_t stgoff = STG0 + (uint32_t)(ck & 1) * STG_SZ;
        const uint32_t stg = sbase + stgoff;

        if (ck < 15) {
            load_chunk(sbase + STG0 + (uint32_t)((ck + 1) & 1) * STG_SZ,
                       (ck + 1) * 32);
            CP_COMMIT();
        }

        // ---- S = Q K^T (3-pass split) ----
        float s[4][4];
#pragma unroll
        for (int i = 0; i < 4; i++)
#pragma unroll
            for (int j = 0; j < 4; j++) s[i][j] = 0.f;

#pragma unroll
        for (int ks = 0; ks < 4; ks++) {
#pragma unroll
            for (int ni = 0; ni < 4; ni++) {
                uint32_t boff = (uint32_t)(ni * 8 + b_row) * AST + b_colb + ks * 32;
                uint32_t bh2[2], bl2[2];
                ldsm_x2(bh2[0], bh2[1], stg + boff);
                ldsm_x2(bl2[0], bl2[1], stg + 4608 + boff);
                mma16816(s[ni], qfh[ks], bh2);
                mma16816(s[ni], qfl[ks], bh2);
                mma16816(s[ni], qfh[ks], bl2);
            }
        }

        // ---- online softmax (exp2 domain) ----
        float alpha[2];
#pragma unroll
        for (int rr = 0; rr < 2; rr++) {
            const float* ep = (const float*)(smem + stgoff + 18432 +
                                             (size_t)(wr + r0 + rr * 8) * AST) + c2;
            float ev[4][2];
            float mx = -1e30f;
#pragma unroll
            for (int j = 0; j < 4; j++) {
                float2 e2 = *(const float2*)(ep + j * 8);
                ev[j][0] = e2.x; ev[j][1] = e2.y;
                float s0 = (e2.x > 0.f) ? s[j][rr * 2] : -1e30f;
                float s1 = (e2.y > 0.f) ? s[j][rr * 2 + 1] : -1e30f;
                s[j][rr * 2] = s0; s[j][rr * 2 + 1] = s1;
                mx = fmaxf(mx, fmaxf(s0, s1));
            }
            mx = fmaxf(mx, __shfl_xor_sync(0xffffffffu, mx, 1));
            mx = fmaxf(mx, __shfl_xor_sync(0xffffffffu, mx, 2));
            float mn = fmaxf(m_r[rr], mx);
            alpha[rr] = exp2r(m_r[rr] - mn);
            m_r[rr] = mn;
            float ls = 0.f;
#pragma unroll
            for (int j = 0; j < 4; j++) {
                float ex0 = exp2r(s[j][rr * 2] - mn);
                float ex1 = exp2r(s[j][rr * 2 + 1] - mn);
                ls += ex0 + ex1;
                s[j][rr * 2] = ex0 * ev[j][0];
                s[j][rr * 2 + 1] = ex1 * ev[j][1];
            }
            ls += __shfl_xor_sync(0xffffffffu, ls, 1);
            ls += __shfl_xor_sync(0xffffffffu, ls, 2);
            l_r[rr] = l_r[rr] * alpha[rr] + ls;
        }

        // ---- rescale ctx, then ctx += P V (V via ldmatrix.trans) ----
#pragma unroll
        for (int ni = 0; ni < 8; ni++) {
            cacc[ni][0] *= alpha[0]; cacc[ni][1] *= alpha[0];
            cacc[ni][2] *= alpha[1]; cacc[ni][3] *= alpha[1];
        }
#pragma unroll
        for (int ks = 0; ks < 2; ks++) {
            const float* t0 = s[2 * ks];
            const float* t1 = s[2 * ks + 1];
            uint32_t ap[4], alp[4];
#pragma unroll
            for (int q = 0; q < 4; q++) {
                const float* tt = (q < 2) ? t0 : t1;
                float v0 = tt[(q & 1) * 2], v1 = tt[(q & 1) * 2 + 1];
                uint32_t hp = pkbf(v0, v1);
                float h0 = __uint_as_float(hp << 16);
                float h1 = __uint_as_float(hp & 0xffff0000u);
                ap[q] = hp;
                alp[q] = pkbf(v0 - h0, v1 - h1);
            }
            uint32_t vrow = (uint32_t)(ks * 16 + (lane & 15)) * AST;
#pragma unroll
            for (int ni = 0; ni < 8; ni++) {
                uint32_t bh2[2], bl2[2];
                ldsm_x2t(bh2[0], bh2[1], stg + 9216 + vrow + ni * 16);
                ldsm_x2t(bl2[0], bl2[1], stg + 13824 + vrow + ni * 16);
                mma16816(cacc[ni], ap, bh2);
                mma16816(cacc[ni], alp, bh2);
                mma16816(cacc[ni], ap, bl2);
            }
        }

        if (ck < 15) {
            CP_WAIT0();
            __syncthreads();
        }
    }

    // ---- finalize ----
    const float inv0 = 1.0f / l_r[0];
    const float inv1 = 1.0f / l_r[1];
    const int row0 = p0 + wr + r0;
#pragma unroll
    for (int ni = 0; ni < 8; ni++) {
        int dh = ni * 8 + c2;
        size_t base0 = ((size_t)b * P + row0) * D + h * DH + dh;
        float2 o0{cacc[ni][0] * inv0, cacc[ni][1] * inv0};
        float2 o1{cacc[ni][2] * inv1, cacc[ni][3] * inv1};
        *(float2*)(ctx + base0) = o0;
        *(float2*)(ctx + base0 + (size_t)8 * D) = o1;
    }
}

// =====================================================================
// LayerNorm over D=1024.
// =====================================================================
__global__ void __launch_bounds__(256) ln_kernel(
    const float* __restrict__ x, const float* __restrict__ gamma,
    const float* __restrict__ beta, float* __restrict__ out)
{
    __shared__ float rs1[8], rs2[8];
    const int row = blockIdx.x;
    const int tid = threadIdx.x;
    const float4 xv = *(const float4*)(x + (size_t)row * D + tid * 4);
    float s1 = xv.x + xv.y + xv.z + xv.w;
    float s2 = xv.x * xv.x + xv.y * xv.y + xv.z * xv.z + xv.w * xv.w;
#pragma unroll
    for (int o = 16; o; o >>= 1) {
        s1 += __shfl_xor_sync(0xffffffffu, s1, o);
        s2 += __shfl_xor_sync(0xffffffffu, s2, o);
    }
    if ((tid & 31) == 0) { rs1[tid >> 5] = s1; rs2[tid >> 5] = s2; }
    __syncthreads();
    if (tid < 32) {
        float t1 = (tid < 8) ? rs1[tid] : 0.f;
        float t2 = (tid < 8) ? rs2[tid] : 0.f;
#pragma unroll
        for (int o = 4; o; o >>= 1) {
            t1 += __shfl_xor_sync(0xffffffffu, t1, o);
            t2 += __shfl_xor_sync(0xffffffffu, t2, o);
        }
        if (tid == 0) { rs1[0] = t1; rs2[0] = t2; }
    }
    __syncthreads();
    const float mu = rs1[0] * (1.0f / D);
    const float var = fmaxf(rs2[0] * (1.0f / D) - mu * mu, 0.f);
    const float r = rsqrtf(var + 1e-6f);
    const float4 g = *(const float4*)(gamma + tid * 4);
    const float4 bt = *(const float4*)(beta + tid * 4);
    float4 o;
    o.x = (xv.x - mu) * r * g.x + bt.x;
    o.y = (xv.y - mu) * r * g.y + bt.y;
    o.z = (xv.z - mu) * r * g.z + bt.z;
    o.w = (xv.w - mu) * r * g.w + bt.w;
    *(float4*)(out + (size_t)row * D + tid * 4) = o;
}

// =====================================================================
extern "C" void kernel_launch(void* const* d_in, const int* in_sizes, int n_in,
                              void* d_out, int out_size)
{
    const float* para    = (const float*)d_in[0];
    const float* cluster = (const float*)d_in[1];
    const float* edge    = (const float*)d_in[2];
    const float* Wq = (const float*)d_in[3];
    const float* bq = (const float*)d_in[4];
    const float* Wk = (const float*)d_in[5];
    const float* bk = (const float*)d_in[6];
    const float* Wv = (const float*)d_in[7];
    const float* bv = (const float*)d_in[8];
    const float* gamma = (const float*)d_in[9];
    const float* beta  = (const float*)d_in[10];
    float* out = (float*)d_out;

    float* cp;
    __nv_bfloat16 *qhp, *qlp, *khp, *klp, *vhp, *vlp;
    __nv_bfloat16 *pah, *pal, *clh, *cll, *wth, *wtl;
    cudaGetSymbolAddress((void**)&cp, g_ctx);
    cudaGetSymbolAddress((void**)&qhp, g_qh);
    cudaGetSymbolAddress((void**)&qlp, g_ql);
    cudaGetSymbolAddress((void**)&khp, g_kh);
    cudaGetSymbolAddress((void**)&klp, g_kl);
    cudaGetSymbolAddress((void**)&vhp, g_vh);
    cudaGetSymbolAddress((void**)&vlp, g_vl);
    cudaGetSymbolAddress((void**)&pah, g_pa_hi);
    cudaGetSymbolAddress((void**)&pal, g_pa_lo);
    cudaGetSymbolAddress((void**)&clh, g_cl_hi);
    cudaGetSymbolAddress((void**)&cll, g_cl_lo);
    cudaGetSymbolAddress((void**)&wth, g_wt_hi);
    cudaGetSymbolAddress((void**)&wtl, g_wt_lo);

    cudaFuncSetAttribute(proj_mma,
                         cudaFuncAttributeMaxDynamicSharedMemorySize,
                         PROJ_SMEM_BYTES);
    cudaFuncSetAttribute(attn_mma,
                         cudaFuncAttributeMaxDynamicSharedMemorySize,
                         ATTN_SMEM_BYTES);

    cvt_split<<<(B * P * D) / (256 * 4), 256>>>(para, pah, pal);
    cvt_split<<<(B * C * D) / (256 * 4), 256>>>(cluster, clh, cll);
    wt_split<<<dim3(32, 32, 3), 256>>>(Wq, Wk, Wv, wth, wtl);

    proj_mma<<<768, 256, PROJ_SMEM_BYTES>>>(pah, pal, clh, cll, wth, wtl,
                                            bq, bk, bv,
                                            qhp, qlp, khp, klp, vhp, vlp);

    attn_mma<<<dim3(P / 128, H, B), 256, ATTN_SMEM_BYTES>>>(
        qhp, qlp, khp, klp, vhp, vlp, edge, cp);

    ln_kernel<<<B * P, 256>>>(cp, gamma, beta, out);
}

// round 7
// speedup vs baseline: 3.3044x; 1.0329x over previous
#include <cuda_runtime.h>
#include <cuda_bf16.h>
#include <math.h>
#include <stdint.h>

#define B 4
#define P 2048
#define C 512
#define D 1024
#define H 16
#define DH 64

// ---------------- scratch (static device arrays) ----------------
__device__ __nv_bfloat16 g_qh[(size_t)B * H * P * DH];
__device__ __nv_bfloat16 g_ql[(size_t)B * H * P * DH];
__device__ __nv_bfloat16 g_kh[(size_t)B * H * C * DH];
__device__ __nv_bfloat16 g_kl[(size_t)B * H * C * DH];
__device__ __nv_bfloat16 g_vh[(size_t)B * H * C * DH];
__device__ __nv_bfloat16 g_vl[(size_t)B * H * C * DH];
__device__ float g_ctx[(size_t)B * P * D];
__device__ __nv_bfloat16 g_pa_hi[(size_t)B * P * D];
__device__ __nv_bfloat16 g_pa_lo[(size_t)B * P * D];
__device__ __nv_bfloat16 g_cl_hi[(size_t)B * C * D];
__device__ __nv_bfloat16 g_cl_lo[(size_t)B * C * D];
__device__ __nv_bfloat16 g_wt_hi[(size_t)3 * D * D];
__device__ __nv_bfloat16 g_wt_lo[(size_t)3 * D * D];

__device__ __forceinline__ uint32_t smem_u32(const void* p) {
    uint32_t a;
    asm("{ .reg .u64 t; cvta.to.shared.u64 t, %1; cvt.u32.u64 %0, t; }"
        : "=r"(a) : "l"(p));
    return a;
}

// ---------------- mma.sync helpers ----------------
__device__ __forceinline__ void ldsm_x4(uint32_t& r0, uint32_t& r1,
                                        uint32_t& r2, uint32_t& r3, uint32_t a) {
    asm volatile("ldmatrix.sync.aligned.m8n8.x4.shared.b16 {%0,%1,%2,%3}, [%4];"
                 : "=r"(r0), "=r"(r1), "=r"(r2), "=r"(r3) : "r"(a));
}
__device__ __forceinline__ void ldsm_x2t(uint32_t& r0, uint32_t& r1, uint32_t a) {
    asm volatile("ldmatrix.sync.aligned.m8n8.x2.trans.shared.b16 {%0,%1}, [%2];"
                 : "=r"(r0), "=r"(r1) : "r"(a));
}
__device__ __forceinline__ void mma16816(float* d, const uint32_t* a,
                                         const uint32_t* b) {
    asm volatile(
        "mma.sync.aligned.m16n8k16.row.col.f32.bf16.bf16.f32 "
        "{%0,%1,%2,%3}, {%4,%5,%6,%7}, {%8,%9}, {%0,%1,%2,%3};"
        : "+f"(d[0]), "+f"(d[1]), "+f"(d[2]), "+f"(d[3])
        : "r"(a[0]), "r"(a[1]), "r"(a[2]), "r"(a[3]), "r"(b[0]), "r"(b[1]));
}
__device__ __forceinline__ void cp16(uint32_t dst, const void* src) {
    asm volatile("cp.async.cg.shared.global [%0], [%1], 16;"
                 :: "r"(dst), "l"(src));
}
#define CP_COMMIT() asm volatile("cp.async.commit_group;" ::: "memory")
#define CP_WAIT0()  asm volatile("cp.async.wait_group 0;" ::: "memory")

__device__ __forceinline__ uint32_t pkbf(float lo, float hi) {
    uint32_t d;
    asm("cvt.rn.bf16x2.f32 %0, %1, %2;" : "=r"(d) : "f"(hi), "f"(lo));
    return d;
}
__device__ __forceinline__ float exp2r(float x) {
    float y; asm("ex2.approx.ftz.f32 %0, %1;" : "=f"(y) : "f"(x)); return y;
}

// =====================================================================
// Merged prep kernel: para split | cluster split | W transpose+split.
// =====================================================================
#define PA_BLKS ((B * P * D) / 1024)      // 8192
#define CL_BLKS ((B * C * D) / 1024)      // 2048
#define WT_BLKS (32 * 32 * 3)             // 3072
#define PREP_BLKS (PA_BLKS + CL_BLKS + WT_BLKS)

__global__ void __launch_bounds__(256) prep_all(
    const float* __restrict__ para, const float* __restrict__ cluster,
    const float* __restrict__ Wq, const float* __restrict__ Wk,
    const float* __restrict__ Wv,
    __nv_bfloat16* __restrict__ pah, __nv_bfloat16* __restrict__ pal,
    __nv_bfloat16* __restrict__ clh, __nv_bfloat16* __restrict__ cll,
    __nv_bfloat16* __restrict__ wth, __nv_bfloat16* __restrict__ wtl)
{
    const int bid = blockIdx.x;
    if (bid < PA_BLKS + CL_BLKS) {
        const float* x;
        __nv_bfloat16 *hi, *lo;
        size_t base;
        if (bid < PA_BLKS) { x = para; hi = pah; lo = pal; base = (size_t)bid * 1024; }
        else { x = cluster; hi = clh; lo = cll; base = (size_t)(bid - PA_BLKS) * 1024; }
        size_t i = base + (size_t)threadIdx.x * 4;
        float4 v = *(const float4*)(x + i);
        __nv_bfloat16 h0 = __float2bfloat16(v.x);
        __nv_bfloat16 h1 = __float2bfloat16(v.y);
        __nv_bfloat16 h2 = __float2bfloat16(v.z);
        __nv_bfloat16 h3 = __float2bfloat16(v.w);
        __nv_bfloat162 hp0{h0, h1}, hp1{h2, h3};
        __nv_bfloat162 lp0{__float2bfloat16(v.x - __bfloat162float(h0)),
                           __float2bfloat16(v.y - __bfloat162float(h1))};
        __nv_bfloat162 lp1{__float2bfloat16(v.z - __bfloat162float(h2)),
                           __float2bfloat16(v.w - __bfloat162float(h3))};
        *(__nv_bfloat162*)(hi + i) = hp0;
        *(__nv_bfloat162*)(hi + i + 2) = hp1;
        *(__nv_bfloat162*)(lo + i) = lp0;
        *(__nv_bfloat162*)(lo + i + 2) = lp1;
        return;
    }
    // W transpose+split
    __shared__ float t[32][33];
    const int wb = bid - PA_BLKS - CL_BLKS;
    const int wz = wb >> 10;                  // 0..2
    const int rem = wb & 1023;
    const int kb = (rem & 31) * 32, nb = (rem >> 5) * 32;
    const float* W = (wz == 0) ? Wq : (wz == 1) ? Wk : Wv;
    size_t ooff = (size_t)wz * D * D;
    int tx = threadIdx.x & 31, ty = threadIdx.x >> 5;
#pragma unroll
    for (int j = 0; j < 4; j++)
        t[ty + j * 8][tx] = W[(size_t)(kb + ty + j * 8) * D + nb + tx];
    __syncthreads();
#pragma unroll
    for (int j = 0; j < 4; j++) {
        int n = nb + ty + j * 8, kk = kb + tx;
        float v = t[tx][ty + j * 8];
        __nv_bfloat16 h = __float2bfloat16(v);
        wth[ooff + (size_t)n * D + kk] = h;
        wtl[ooff + (size_t)n * D + kk] = __float2bfloat16(v - __bfloat162float(h));
    }
}

// =====================================================================
// Projection GEMM via mma.sync split-bf16, pass-major inner loops,
// B fragments via ldsm_x4.
// =====================================================================
#define SST 40
#define ARR_B (128 * SST * 2)
#define STAGE_B (4 * ARR_B)
#define PROJ_SMEM_BYTES (2 * STAGE_B)

__global__ void __launch_bounds__(256, 2) proj_mma(
    const __nv_bfloat16* __restrict__ pa_hi, const __nv_bfloat16* __restrict__ pa_lo,
    const __nv_bfloat16* __restrict__ cl_hi, const __nv_bfloat16* __restrict__ cl_lo,
    const __nv_bfloat16* __restrict__ wt_hi, const __nv_bfloat16* __restrict__ wt_lo,
    const float* __restrict__ bq, const float* __restrict__ bk,
    const float* __restrict__ bv,
    __nv_bfloat16* __restrict__ qh, __nv_bfloat16* __restrict__ ql,
    __nv_bfloat16* __restrict__ kh, __nv_bfloat16* __restrict__ kl,
    __nv_bfloat16* __restrict__ vh, __nv_bfloat16* __restrict__ vl)
{
    extern __shared__ char smem[];
    const uint32_t sbase = smem_u32(smem);
    const int tid = threadIdx.x;
    const int wid = tid >> 5, lane = tid & 31;

    const int bid = blockIdx.x;
    const __nv_bfloat16 *Xh, *Xl, *Wh, *Wl;
    const float* bias;
    __nv_bfloat16 *oh, *ol;
    int mblk, Lsh; float scale;
    if (bid < 512) {
        Xh = pa_hi; Xl = pa_lo; Wh = wt_hi; Wl = wt_lo;
        bias = bq; oh = qh; ol = ql; Lsh = 11;
        scale = 0.125f * 1.44269504f;
        mblk = bid >> 3;
    } else if (bid < 640) {
        Xh = cl_hi; Xl = cl_lo; Wh = wt_hi + (size_t)D * D; Wl = wt_lo + (size_t)D * D;
        bias = bk; oh = kh; ol = kl; Lsh = 9; scale = 1.0f; mblk = (bid - 512) >> 3;
    } else {
        Xh = cl_hi; Xl = cl_lo; Wh = wt_hi + (size_t)2 * D * D; Wl = wt_lo + (size_t)2 * D * D;
        bias = bv; oh = vh; ol = vl; Lsh = 9; scale = 1.0f; mblk = (bid - 640) >> 3;
    }
    const int n0 = (bid & 7) * 128;
    const int m0 = mblk * 128;

    const int wm = wid >> 2, wn = wid & 3;
    const int r0l = tid >> 2, s0l = (tid & 3);
    const int r1l = (tid + 256) >> 2, s1l = ((tid + 256) & 3);

    auto stage_load = [&](int stg, int k0) {
        const uint32_t sb = sbase + (uint32_t)stg * STAGE_B;
        const __nv_bfloat16* srcs[4] = {Xh, Xl, Wh, Wl};
        const int rowoff[4] = {m0, m0, n0, n0};
#pragma unroll
        for (int a = 0; a < 4; a++) {
            const __nv_bfloat16* s = srcs[a];
            uint32_t ab = sb + a * ARR_B;
            cp16(ab + r0l * (SST * 2) + s0l * 16,
                 s + (size_t)(rowoff[a] + r0l) * D + k0 + s0l * 8);
            cp16(ab + r1l * (SST * 2) + s1l * 16,
                 s + (size_t)(rowoff[a] + r1l) * D + k0 + s1l * 8);
        }
    };

    float acc[4][4][4];
#pragma unroll
    for (int i = 0; i < 4; i++)
#pragma unroll
        for (int j = 0; j < 4; j++)
#pragma unroll
            for (int q = 0; q < 4; q++) acc[i][j][q] = 0.f;

    const int a_row_in = (lane & 7) + 8 * ((lane >> 3) & 1);
    const int a_colb = (lane >> 4) * 16;
    // x4 B mapping: pair of adjacent n8 tiles
    const int b4_row = ((lane >> 4) & 1) * 8 + (lane & 7);
    const int b4_colb = ((lane >> 3) & 1) * 16;

    stage_load(0, 0);
    CP_COMMIT();
    CP_WAIT0();
    __syncthreads();

    for (int ck = 0; ck < 32; ck++) {
        if (ck < 31) {
            stage_load((ck + 1) & 1, (ck + 1) * 32);
            CP_COMMIT();
        }
        const uint32_t sb = sbase + (uint32_t)(ck & 1) * STAGE_B;
        const uint32_t xh = sb, xl = sb + ARR_B, wh = sb + 2 * ARR_B, wl = sb + 3 * ARR_B;

#pragma unroll
        for (int ks = 0; ks < 2; ks++) {
            const int kb = ks * 32;
            uint32_t bhi[4][2], blo[4][2];
#pragma unroll
            for (int pi = 0; pi < 2; pi++) {
                uint32_t boff =
                    (uint32_t)(wn * 32 + pi * 16 + b4_row) * (SST * 2) + kb + b4_colb;
                ldsm_x4(bhi[2 * pi][0], bhi[2 * pi][1],
                        bhi[2 * pi + 1][0], bhi[2 * pi + 1][1], wh + boff);
                ldsm_x4(blo[2 * pi][0], blo[2 * pi][1],
                        blo[2 * pi + 1][0], blo[2 * pi + 1][1], wl + boff);
            }
#pragma unroll
            for (int mi = 0; mi < 4; mi++) {
                uint32_t aoff =
                    (uint32_t)(wm * 64 + mi * 16 + a_row_in) * (SST * 2) + kb + a_colb;
                uint32_t ahi[4], alo[4];
                ldsm_x4(ahi[0], ahi[1], ahi[2], ahi[3], xh + aoff);
                ldsm_x4(alo[0], alo[1], alo[2], alo[3], xl + aoff);
                // pass-major: 4 independent acc chains per pass
#pragma unroll
                for (int ni = 0; ni < 4; ni++) mma16816(acc[mi][ni], ahi, bhi[ni]);
#pragma unroll
                for (int ni = 0; ni < 4; ni++) mma16816(acc[mi][ni], ahi, blo[ni]);
#pragma unroll
                for (int ni = 0; ni < 4; ni++) mma16816(acc[mi][ni], alo, bhi[ni]);
            }
        }
        CP_WAIT0();
        __syncthreads();
    }

    const int qr = lane >> 2;
    const int qc = (lane & 3) * 2;
    const int L = 1 << Lsh, Lm = L - 1;
#pragma unroll
    for (int mi = 0; mi < 4; mi++) {
#pragma unroll
        for (int rh = 0; rh < 2; rh++) {
            int m = m0 + wm * 64 + mi * 16 + qr + rh * 8;
            int bb = m >> Lsh, l = m & Lm;
#pragma unroll
            for (int ni = 0; ni < 4; ni++) {
                int n = n0 + wn * 32 + ni * 8 + qc;
                int hh = n >> 6, d0 = n & 63;
                float ox = (acc[mi][ni][rh * 2 + 0] + bias[n]) * scale;
                float oy = (acc[mi][ni][rh * 2 + 1] + bias[n + 1]) * scale;
                uint32_t hp = pkbf(ox, oy);
                float hx = __uint_as_float(hp << 16);
                float hy = __uint_as_float(hp & 0xffff0000u);
                uint32_t lp = pkbf(ox - hx, oy - hy);
                size_t off = (((size_t)bb * H + hh) * (size_t)L + l) * DH + d0;
                *(uint32_t*)(oh + off) = hp;
                *(uint32_t*)(ol + off) = lp;
            }
        }
    }
}

// =====================================================================
// Fused attention: CT=32 double-buffered pipeline, pass-major MMA
// ordering, K fragments via ldsm_x4, V via ldsm_x2.trans.
// =====================================================================
#define AST 144
#define STG0 36864
#define STG_SZ 36864
#define ATTN_SMEM_BYTES (STG0 + 2 * STG_SZ)

__global__ void __launch_bounds__(256, 2) attn_mma(
    const __nv_bfloat16* __restrict__ qh, const __nv_bfloat16* __restrict__ ql,
    const __nv_bfloat16* __restrict__ kh, const __nv_bfloat16* __restrict__ kl,
    const __nv_bfloat16* __restrict__ vh, const __nv_bfloat16* __restrict__ vl,
    const float* __restrict__ edge, float* __restrict__ ctx)
{
    extern __shared__ char smem[];
    const uint32_t sbase = smem_u32(smem);
    const int tid = threadIdx.x;
    const int wid = tid >> 5, lane = tid & 31;
    const int b = blockIdx.z, h = blockIdx.y;
    const int p0 = blockIdx.x * 128;

    const size_t qoff = (((size_t)b * H + h) * P + p0) * DH;
    const size_t koff = (((size_t)b * H + h) * C) * DH;
    const float* ebase = edge + ((size_t)b * P + p0) * C;

    const int krow = tid >> 3, kseg = tid & 7;
    const __nv_bfloat16* kvarr[4] = {kh, kl, vh, vl};

    auto load_chunk = [&](uint32_t stg, int cn) {
#pragma unroll
        for (int q = 0; q < 4; q++)
            cp16(stg + q * 4608 + krow * AST + kseg * 16,
                 kvarr[q] + koff + (size_t)(cn + krow) * DH + kseg * 8);
#pragma unroll
        for (int i = 0; i < 4; i++) {
            int er = (tid + i * 256) >> 3;
            cp16(stg + 18432 + er * AST + kseg * 16,
                 ebase + (size_t)er * C + cn + kseg * 4);
        }
    };

#pragma unroll
    for (int i = 0; i < 8; i++) {
        int g = tid + i * 256;
        int arr = g >> 10, rem = g & 1023;
        int row = rem >> 3, seg = rem & 7;
        cp16(sbase + arr * 18432 + row * AST + seg * 16,
             (arr ? ql : qh) + qoff + (size_t)row * DH + seg * 8);
    }
    load_chunk(sbase + STG0, 0);
    CP_COMMIT();

    const int a_row = (lane & 7) + 8 * ((lane >> 3) & 1);
    const int a_colb = (lane >> 4) * 16;
    const int b4_row = ((lane >> 4) & 1) * 8 + (lane & 7);
    const int b4_colb = ((lane >> 3) & 1) * 16;
    const int r0 = lane >> 2;
    const int wr = wid * 16;
    const int c2 = (lane & 3) * 2;

    CP_WAIT0();
    __syncthreads();

    uint32_t qfh[4][4], qfl[4][4];
#pragma unroll
    for (int ks = 0; ks < 4; ks++) {
        uint32_t aoff = (uint32_t)(wr + a_row) * AST + a_colb + ks * 32;
        ldsm_x4(qfh[ks][0], qfh[ks][1], qfh[ks][2], qfh[ks][3], sbase + aoff);
        ldsm_x4(qfl[ks][0], qfl[ks][1], qfl[ks][2], qfl[ks][3],
                sbase + 18432 + aoff);
    }

    float m_r[2] = {-1e30f, -1e30f};
    float l_r[2] = {0.f, 0.f};
    float cacc[8][4];
#pragma unroll
    for (int i = 0; i < 8; i++)
#pragma unroll
        for (int j = 0; j < 4; j++) cacc[i][j] = 0.f;

    for (int ck = 0; ck < 16; ck++) {
        const uint32_t stgoff = STG0 + (uint32_t)(ck & 1) * STG_SZ;
        const uint32_t stg = sbase + stgoff;

        if (ck < 15) {
            load_chunk(sbase + STG0 + (uint32_t)((ck + 1) & 1) * STG_SZ,
                       (ck + 1) * 32);
            CP_COMMIT();
        }

        // ---- S = Q K^T, pass-major ----
        float s[4][4];
#pragma unroll
        for (int i = 0; i < 4; i++)
#pragma unroll
            for (int j = 0; j < 4; j++) s[i][j] = 0.f;

#pragma unroll
        for (int ks = 0; ks < 4; ks++) {
            uint32_t bh2[4][2], bl2[4][2];
#pragma unroll
            for (int pi = 0; pi < 2; pi++) {
                uint32_t boff =
                    (uint32_t)(pi * 16 + b4_row) * AST + b4_colb + ks * 32;
                ldsm_x4(bh2[2 * pi][0], bh2[2 * pi][1],
                        bh2[2 * pi + 1][0], bh2[2 * pi + 1][1], stg + boff);
                ldsm_x4(bl2[2 * pi][0], bl2[2 * pi][1],
                        bl2[2 * pi + 1][0], bl2[2 * pi + 1][1], stg + 4608 + boff);
            }
#pragma unroll
            for (int ni = 0; ni < 4; ni++) mma16816(s[ni], qfh[ks], bh2[ni]);
#pragma unroll
            for (int ni = 0; ni < 4; ni++) mma16816(s[ni], qfl[ks], bh2[ni]);
#pragma unroll
            for (int ni = 0; ni < 4; ni++) mma16816(s[ni], qfh[ks], bl2[ni]);
        }

        // ---- online softmax (exp2 domain) ----
        float alpha[2];
#pragma unroll
        for (int rr = 0; rr < 2; rr++) {
            const float* ep = (const float*)(smem + stgoff + 18432 +
                                             (size_t)(wr + r0 + rr * 8) * AST) + c2;
            float ev[4][2];
            float mx = -1e30f;
#pragma unroll
            for (int j = 0; j < 4; j++) {
                float2 e2 = *(const float2*)(ep + j * 8);
                ev[j][0] = e2.x; ev[j][1] = e2.y;
                float s0 = (e2.x > 0.f) ? s[j][rr * 2] : -1e30f;
                float s1 = (e2.y > 0.f) ? s[j][rr * 2 + 1] : -1e30f;
                s[j][rr * 2] = s0; s[j][rr * 2 + 1] = s1;
                mx = fmaxf(mx, fmaxf(s0, s1));
            }
            mx = fmaxf(mx, __shfl_xor_sync(0xffffffffu, mx, 1));
            mx = fmaxf(mx, __shfl_xor_sync(0xffffffffu, mx, 2));
            float mn = fmaxf(m_r[rr], mx);
            alpha[rr] = exp2r(m_r[rr] - mn);
            m_r[rr] = mn;
            float ls = 0.f;
#pragma unroll
            for (int j = 0; j < 4; j++) {
                float ex0 = exp2r(s[j][rr * 2] - mn);
                float ex1 = exp2r(s[j][rr * 2 + 1] - mn);
                ls += ex0 + ex1;
                s[j][rr * 2] = ex0 * ev[j][0];
                s[j][rr * 2 + 1] = ex1 * ev[j][1];
            }
            ls += __shfl_xor_sync(0xffffffffu, ls, 1);
            ls += __shfl_xor_sync(0xffffffffu, ls, 2);
            l_r[rr] = l_r[rr] * alpha[rr] + ls;
        }

        // ---- rescale ctx, then ctx += P V (pass-major over 8 ni) ----
#pragma unroll
        for (int ni = 0; ni < 8; ni++) {
            cacc[ni][0] *= alpha[0]; cacc[ni][1] *= alpha[0];
            cacc[ni][2] *= alpha[1]; cacc[ni][3] *= alpha[1];
        }
#pragma unroll
        for (int ks = 0; ks < 2; ks++) {
            const float* t0 = s[2 * ks];
            const float* t1 = s[2 * ks + 1];
            uint32_t ap[4], alp[4];
#pragma unroll
            for (int q = 0; q < 4; q++) {
                const float* tt = (q < 2) ? t0 : t1;
                float v0 = tt[(q & 1) * 2], v1 = tt[(q & 1) * 2 + 1];
                uint32_t hp = pkbf(v0, v1);
                float h0 = __uint_as_float(hp << 16);
                float h1 = __uint_as_float(hp & 0xffff0000u);
                ap[q] = hp;
                alp[q] = pkbf(v0 - h0, v1 - h1);
            }
            uint32_t vrow = (uint32_t)(ks * 16 + (lane & 15)) * AST;
            uint32_t vh2[8][2], vl2[8][2];
#pragma unroll
            for (int ni = 0; ni < 8; ni++) {
                ldsm_x2t(vh2[ni][0], vh2[ni][1], stg + 9216 + vrow + ni * 16);
                ldsm_x2t(vl2[ni][0], vl2[ni][1], stg + 13824 + vrow + ni * 16);
            }
#pragma unroll
            for (int ni = 0; ni < 8; ni++) mma16816(cacc[ni], ap, vh2[ni]);
#pragma unroll
            for (int ni = 0; ni < 8; ni++) mma16816(cacc[ni], alp, vh2[ni]);
#pragma unroll
            for (int ni = 0; ni < 8; ni++) mma16816(cacc[ni], ap, vl2[ni]);
        }

        if (ck < 15) {
            CP_WAIT0();
            __syncthreads();
        }
    }

    const float inv0 = 1.0f / l_r[0];
    const float inv1 = 1.0f / l_r[1];
    const int row0 = p0 + wr + r0;
#pragma unroll
    for (int ni = 0; ni < 8; ni++) {
        int dh = ni * 8 + c2;
        size_t base0 = ((size_t)b * P + row0) * D + h * DH + dh;
        float2 o0{cacc[ni][0] * inv0, cacc[ni][1] * inv0};
        float2 o1{cacc[ni][2] * inv1, cacc[ni][3] * inv1};
        *(float2*)(ctx + base0) = o0;
        *(float2*)(ctx + base0 + (size_t)8 * D) = o1;
    }
}

// =====================================================================
// LayerNorm over D=1024.
// =====================================================================
__global__ void __launch_bounds__(256) ln_kernel(
    const float* __restrict__ x, const float* __restrict__ gamma,
    const float* __restrict__ beta, float* __restrict__ out)
{
    __shared__ float rs1[8], rs2[8];
    const int row = blockIdx.x;
    const int tid = threadIdx.x;
    const float4 xv = *(const float4*)(x + (size_t)row * D + tid * 4);
    float s1 = xv.x + xv.y + xv.z + xv.w;
    float s2 = xv.x * xv.x + xv.y * xv.y + xv.z * xv.z + xv.w * xv.w;
#pragma unroll
    for (int o = 16; o; o >>= 1) {
        s1 += __shfl_xor_sync(0xffffffffu, s1, o);
        s2 += __shfl_xor_sync(0xffffffffu, s2, o);
    }
    if ((tid & 31) == 0) { rs1[tid >> 5] = s1; rs2[tid >> 5] = s2; }
    __syncthreads();
    if (tid < 32) {
        float t1 = (tid < 8) ? rs1[tid] : 0.f;
        float t2 = (tid < 8) ? rs2[tid] : 0.f;
#pragma unroll
        for (int o = 4; o; o >>= 1) {
            t1 += __shfl_xor_sync(0xffffffffu, t1, o);
            t2 += __shfl_xor_sync(0xffffffffu, t2, o);
        }
        if (tid == 0) { rs1[0] = t1; rs2[0] = t2; }
    }
    __syncthreads();
    const float mu = rs1[0] * (1.0f / D);
    const float var = fmaxf(rs2[0] * (1.0f / D) - mu * mu, 0.f);
    const float r = rsqrtf(var + 1e-6f);
    const float4 g = *(const float4*)(gamma + tid * 4);
    const float4 bt = *(const float4*)(beta + tid * 4);
    float4 o;
    o.x = (xv.x - mu) * r * g.x + bt.x;
    o.y = (xv.y - mu) * r * g.y + bt.y;
    o.z = (xv.z - mu) * r * g.z + bt.z;
    o.w = (xv.w - mu) * r * g.w + bt.w;
    *(float4*)(out + (size_t)row * D + tid * 4) = o;
}

// =====================================================================
extern "C" void kernel_launch(void* const* d_in, const int* in_sizes, int n_in,
                              void* d_out, int out_size)
{
    const float* para    = (const float*)d_in[0];
    const float* cluster = (const float*)d_in[1];
    const float* edge    = (const float*)d_in[2];
    const float* Wq = (const float*)d_in[3];
    const float* bq = (const float*)d_in[4];
    const float* Wk = (const float*)d_in[5];
    const float* bk = (const float*)d_in[6];
    const float* Wv = (const float*)d_in[7];
    const float* bv = (const float*)d_in[8];
    const float* gamma = (const float*)d_in[9];
    const float* beta  = (const float*)d_in[10];
    float* out = (float*)d_out;

    float* cp;
    __nv_bfloat16 *qhp, *qlp, *khp, *klp, *vhp, *vlp;
    __nv_bfloat16 *pah, *pal, *clh, *cll, *wth, *wtl;
    cudaGetSymbolAddress((void**)&cp, g_ctx);
    cudaGetSymbolAddress((void**)&qhp, g_qh);
    cudaGetSymbolAddress((void**)&qlp, g_ql);
    cudaGetSymbolAddress((void**)&khp, g_kh);
    cudaGetSymbolAddress((void**)&klp, g_kl);
    cudaGetSymbolAddress((void**)&vhp, g_vh);
    cudaGetSymbolAddress((void**)&vlp, g_vl);
    cudaGetSymbolAddress((void**)&pah, g_pa_hi);
    cudaGetSymbolAddress((void**)&pal, g_pa_lo);
    cudaGetSymbolAddress((void**)&clh, g_cl_hi);
    cudaGetSymbolAddress((void**)&cll, g_cl_lo);
    cudaGetSymbolAddress((void**)&wth, g_wt_hi);
    cudaGetSymbolAddress((void**)&wtl, g_wt_lo);

    cudaFuncSetAttribute(proj_mma,
                         cudaFuncAttributeMaxDynamicSharedMemorySize,
                         PROJ_SMEM_BYTES);
    cudaFuncSetAttribute(attn_mma,
                         cudaFuncAttributeMaxDynamicSharedMemorySize,
                         ATTN_SMEM_BYTES);

    prep_all<<<PREP_BLKS, 256>>>(para, cluster, Wq, Wk, Wv,
                                 pah, pal, clh, cll, wth, wtl);

    proj_mma<<<768, 256, PROJ_SMEM_BYTES>>>(pah, pal, clh, cll, wth, wtl,
                                            bq, bk, bv,
                                            qhp, qlp, khp, klp, vhp, vlp);

    attn_mma<<<dim3(P / 128, H, B), 256, ATTN_SMEM_BYTES>>>(
        qhp, qlp, khp, klp, vhp, vlp, edge, cp);

    ln_kernel<<<B * P, 256>>>(cp, gamma, beta, out);
}

// round 8
// speedup vs baseline: 4.3722x; 1.3231x over previous
#include <cuda_runtime.h>
#include <cuda_fp16.h>
#include <math.h>
#include <stdint.h>

#define B 4
#define P 2048
#define C 512
#define D 1024
#define H 16
#define DH 64

// ---------------- scratch (static device arrays) ----------------
__device__ __half g_qh[(size_t)B * H * P * DH];
__device__ __half g_ql[(size_t)B * H * P * DH];
__device__ __half g_kh[(size_t)B * H * C * DH];
__device__ __half g_vh[(size_t)B * H * C * DH];
__device__ float g_ctx[(size_t)B * P * D];
__device__ __half g_pa_hi[(size_t)B * P * D];
__device__ __half g_pa_lo[(size_t)B * P * D];
__device__ __half g_cl_hi[(size_t)B * C * D];
__device__ __half g_cl_lo[(size_t)B * C * D];
__device__ __half g_wt_hi[(size_t)3 * D * D];

__device__ __forceinline__ uint32_t smem_u32(const void* p) {
    uint32_t a;
    asm("{ .reg .u64 t; cvta.to.shared.u64 t, %1; cvt.u32.u64 %0, t; }"
        : "=r"(a) : "l"(p));
    return a;
}

// ---------------- mma.sync helpers (fp16 in, fp32 accum) ----------------
__device__ __forceinline__ void ldsm_x4(uint32_t& r0, uint32_t& r1,
                                        uint32_t& r2, uint32_t& r3, uint32_t a) {
    asm volatile("ldmatrix.sync.aligned.m8n8.x4.shared.b16 {%0,%1,%2,%3}, [%4];"
                 : "=r"(r0), "=r"(r1), "=r"(r2), "=r"(r3) : "r"(a));
}
__device__ __forceinline__ void ldsm_x2t(uint32_t& r0, uint32_t& r1, uint32_t a) {
    asm volatile("ldmatrix.sync.aligned.m8n8.x2.trans.shared.b16 {%0,%1}, [%2];"
                 : "=r"(r0), "=r"(r1) : "r"(a));
}
__device__ __forceinline__ void mma16816(float* d, const uint32_t* a,
                                         const uint32_t* b) {
    asm volatile(
        "mma.sync.aligned.m16n8k16.row.col.f32.f16.f16.f32 "
        "{%0,%1,%2,%3}, {%4,%5,%6,%7}, {%8,%9}, {%0,%1,%2,%3};"
        : "+f"(d[0]), "+f"(d[1]), "+f"(d[2]), "+f"(d[3])
        : "r"(a[0]), "r"(a[1]), "r"(a[2]), "r"(a[3]), "r"(b[0]), "r"(b[1]));
}
__device__ __forceinline__ void cp16(uint32_t dst, const void* src) {
    asm volatile("cp.async.cg.shared.global [%0], [%1], 16;"
                 :: "r"(dst), "l"(src));
}
#define CP_COMMIT() asm volatile("cp.async.commit_group;" ::: "memory")
#define CP_WAIT0()  asm volatile("cp.async.wait_group 0;" ::: "memory")

// pack two f32 -> f16x2 (first arg in LOW half)
__device__ __forceinline__ uint32_t pkhf(float lo, float hi) {
    uint32_t d;
    asm("cvt.rn.f16x2.f32 %0, %1, %2;" : "=r"(d) : "f"(hi), "f"(lo));
    return d;
}
__device__ __forceinline__ float2 uphf(uint32_t v) {
    __half2 h = *reinterpret_cast<__half2*>(&v);
    return __half22float2(h);          // .x = low half, .y = high half
}
__device__ __forceinline__ float exp2r(float x) {
    float y; asm("ex2.approx.ftz.f32 %0, %1;" : "=f"(y) : "f"(x)); return y;
}

// =====================================================================
// Merged prep: para/cluster split (fp16 hi+lo) | W transpose (fp16 hi).
// =====================================================================
#define PA_BLKS ((B * P * D) / 1024)      // 8192
#define CL_BLKS ((B * C * D) / 1024)      // 2048
#define WT_BLKS (32 * 32 * 3)             // 3072
#define PREP_BLKS (PA_BLKS + CL_BLKS + WT_BLKS)

__global__ void __launch_bounds__(256) prep_all(
    const float* __restrict__ para, const float* __restrict__ cluster,
    const float* __restrict__ Wq, const float* __restrict__ Wk,
    const float* __restrict__ Wv,
    __half* __restrict__ pah, __half* __restrict__ pal,
    __half* __restrict__ clh, __half* __restrict__ cll,
    __half* __restrict__ wth)
{
    const int bid = blockIdx.x;
    if (bid < PA_BLKS + CL_BLKS) {
        const float* x;
        __half *hi, *lo;
        size_t base;
        if (bid < PA_BLKS) { x = para; hi = pah; lo = pal; base = (size_t)bid * 1024; }
        else { x = cluster; hi = clh; lo = cll; base = (size_t)(bid - PA_BLKS) * 1024; }
        size_t i = base + (size_t)threadIdx.x * 4;
        float4 v = *(const float4*)(x + i);
        __half h0 = __float2half_rn(v.x);
        __half h1 = __float2half_rn(v.y);
        __half h2 = __float2half_rn(v.z);
        __half h3 = __float2half_rn(v.w);
        __half2 hp0{h0, h1}, hp1{h2, h3};
        __half2 lp0{__float2half_rn(v.x - __half2float(h0)),
                    __float2half_rn(v.y - __half2float(h1))};
        __half2 lp1{__float2half_rn(v.z - __half2float(h2)),
                    __float2half_rn(v.w - __half2float(h3))};
        *(__half2*)(hi + i) = hp0;
        *(__half2*)(hi + i + 2) = hp1;
        *(__half2*)(lo + i) = lp0;
        *(__half2*)(lo + i + 2) = lp1;
        return;
    }
    // W transpose (fp16 hi only)
    __shared__ float t[32][33];
    const int wb = bid - PA_BLKS - CL_BLKS;
    const int wz = wb >> 10;
    const int rem = wb & 1023;
    const int kb = (rem & 31) * 32, nb = (rem >> 5) * 32;
    const float* W = (wz == 0) ? Wq : (wz == 1) ? Wk : Wv;
    size_t ooff = (size_t)wz * D * D;
    int tx = threadIdx.x & 31, ty = threadIdx.x >> 5;
#pragma unroll
    for (int j = 0; j < 4; j++)
        t[ty + j * 8][tx] = W[(size_t)(kb + ty + j * 8) * D + nb + tx];
    __syncthreads();
#pragma unroll
    for (int j = 0; j < 4; j++) {
        int n = nb + ty + j * 8, kk = kb + tx;
        wth[ooff + (size_t)n * D + kk] = __float2half_rn(t[tx][ty + j * 8]);
    }
}

// =====================================================================
// Projection GEMM: fp16 2-pass (X_hi·W + X_lo·W), W single fp16.
// 128x128 tile, K chunks of 32, cp.async double buffer, 3 smem arrays.
// =====================================================================
#define SST 40
#define ARR_B (128 * SST * 2)             // 10240
#define STAGE_B (3 * ARR_B)               // 30720
#define PROJ_SMEM_BYTES (2 * STAGE_B)

__global__ void __launch_bounds__(256, 2) proj_mma(
    const __half* __restrict__ pa_hi, const __half* __restrict__ pa_lo,
    const __half* __restrict__ cl_hi, const __half* __restrict__ cl_lo,
    const __half* __restrict__ wt_hi,
    const float* __restrict__ bq, const float* __restrict__ bk,
    const float* __restrict__ bv,
    __half* __restrict__ qh, __half* __restrict__ ql,
    __half* __restrict__ kh, __half* __restrict__ vh)
{
    extern __shared__ char smem[];
    const uint32_t sbase = smem_u32(smem);
    const int tid = threadIdx.x;
    const int wid = tid >> 5, lane = tid & 31;

    const int bid = blockIdx.x;
    const __half *Xh, *Xl, *Wh;
    const float* bias;
    __half *oh, *ol;
    int mblk, Lsh; float scale; bool qmode;
    if (bid < 512) {
        Xh = pa_hi; Xl = pa_lo; Wh = wt_hi;
        bias = bq; oh = qh; ol = ql; Lsh = 11;
        scale = 0.125f * 1.44269504f;
        mblk = bid >> 3; qmode = true;
    } else if (bid < 640) {
        Xh = cl_hi; Xl = cl_lo; Wh = wt_hi + (size_t)D * D;
        bias = bk; oh = kh; ol = nullptr; Lsh = 9; scale = 1.0f;
        mblk = (bid - 512) >> 3; qmode = false;
    } else {
        Xh = cl_hi; Xl = cl_lo; Wh = wt_hi + (size_t)2 * D * D;
        bias = bv; oh = vh; ol = nullptr; Lsh = 9; scale = 1.0f;
        mblk = (bid - 640) >> 3; qmode = false;
    }
    const int n0 = (bid & 7) * 128;
    const int m0 = mblk * 128;

    const int wm = wid >> 2, wn = wid & 3;
    const int r0l = tid >> 2, s0l = (tid & 3);
    const int r1l = (tid + 256) >> 2, s1l = ((tid + 256) & 3);

    auto stage_load = [&](int stg, int k0) {
        const uint32_t sb = sbase + (uint32_t)stg * STAGE_B;
        const __half* srcs[3] = {Xh, Xl, Wh};
        const int rowoff[3] = {m0, m0, n0};
#pragma unroll
        for (int a = 0; a < 3; a++) {
            const __half* s = srcs[a];
            uint32_t ab = sb + a * ARR_B;
            cp16(ab + r0l * (SST * 2) + s0l * 16,
                 s + (size_t)(rowoff[a] + r0l) * D + k0 + s0l * 8);
            cp16(ab + r1l * (SST * 2) + s1l * 16,
                 s + (size_t)(rowoff[a] + r1l) * D + k0 + s1l * 8);
        }
    };

    float acc[4][4][4];
#pragma unroll
    for (int i = 0; i < 4; i++)
#pragma unroll
        for (int j = 0; j < 4; j++)
#pragma unroll
            for (int q = 0; q < 4; q++) acc[i][j][q] = 0.f;

    const int a_row_in = (lane & 7) + 8 * ((lane >> 3) & 1);
    const int a_colb = (lane >> 4) * 16;
    const int b4_row = ((lane >> 4) & 1) * 8 + (lane & 7);
    const int b4_colb = ((lane >> 3) & 1) * 16;

    stage_load(0, 0);
    CP_COMMIT();
    CP_WAIT0();
    __syncthreads();

    for (int ck = 0; ck < 32; ck++) {
        if (ck < 31) {
            stage_load((ck + 1) & 1, (ck + 1) * 32);
            CP_COMMIT();
        }
        const uint32_t sb = sbase + (uint32_t)(ck & 1) * STAGE_B;
        const uint32_t xh = sb, xl = sb + ARR_B, wh = sb + 2 * ARR_B;

#pragma unroll
        for (int ks = 0; ks < 2; ks++) {
            const int kb = ks * 32;
            uint32_t bhi[4][2];
#pragma unroll
            for (int pi = 0; pi < 2; pi++) {
                uint32_t boff =
                    (uint32_t)(wn * 32 + pi * 16 + b4_row) * (SST * 2) + kb + b4_colb;
                ldsm_x4(bhi[2 * pi][0], bhi[2 * pi][1],
                        bhi[2 * pi + 1][0], bhi[2 * pi + 1][1], wh + boff);
            }
#pragma unroll
            for (int mi = 0; mi < 4; mi++) {
                uint32_t aoff =
                    (uint32_t)(wm * 64 + mi * 16 + a_row_in) * (SST * 2) + kb + a_colb;
                uint32_t ahi[4], alo[4];
                ldsm_x4(ahi[0], ahi[1], ahi[2], ahi[3], xh + aoff);
                ldsm_x4(alo[0], alo[1], alo[2], alo[3], xl + aoff);
#pragma unroll
                for (int ni = 0; ni < 4; ni++) mma16816(acc[mi][ni], ahi, bhi[ni]);
#pragma unroll
                for (int ni = 0; ni < 4; ni++) mma16816(acc[mi][ni], alo, bhi[ni]);
            }
        }
        CP_WAIT0();
        __syncthreads();
    }

    // epilogue
    const int qr = lane >> 2;
    const int qc = (lane & 3) * 2;
    const int L = 1 << Lsh, Lm = L - 1;
#pragma unroll
    for (int mi = 0; mi < 4; mi++) {
#pragma unroll
        for (int rh = 0; rh < 2; rh++) {
            int m = m0 + wm * 64 + mi * 16 + qr + rh * 8;
            int bb = m >> Lsh, l = m & Lm;
#pragma unroll
            for (int ni = 0; ni < 4; ni++) {
                int n = n0 + wn * 32 + ni * 8 + qc;
                int hh = n >> 6, d0 = n & 63;
                float ox = (acc[mi][ni][rh * 2 + 0] + bias[n]) * scale;
                float oy = (acc[mi][ni][rh * 2 + 1] + bias[n + 1]) * scale;
                uint32_t hp = pkhf(ox, oy);
                size_t off = (((size_t)bb * H + hh) * (size_t)L + l) * DH + d0;
                *(uint32_t*)(oh + off) = hp;
                if (qmode) {
                    float2 hf = uphf(hp);
                    *(uint32_t*)(ol + off) = pkhf(ox - hf.x, oy - hf.y);
                }
            }
        }
    }
}

// =====================================================================
// Fused attention: fp16 2-pass (Q_hi·K + Q_lo·K; P_hi·V + P_lo·V),
// K,V single fp16; CT=32 double-buffered cp.async pipeline.
// =====================================================================
#define AST 144
#define STG0 36864                 // Q hi (18432) + Q lo (18432)
#define STG_SZ 27648               // KH 0, VH 4608, E 9216 (f32 x32/row)
#define ATTN_SMEM_BYTES (STG0 + 2 * STG_SZ)

__global__ void __launch_bounds__(256, 2) attn_mma(
    const __half* __restrict__ qh, const __half* __restrict__ ql,
    const __half* __restrict__ kh, const __half* __restrict__ vh,
    const float* __restrict__ edge, float* __restrict__ ctx)
{
    extern __shared__ char smem[];
    const uint32_t sbase = smem_u32(smem);
    const int tid = threadIdx.x;
    const int wid = tid >> 5, lane = tid & 31;
    const int b = blockIdx.z, h = blockIdx.y;
    const int p0 = blockIdx.x * 128;

    const size_t qoff = (((size_t)b * H + h) * P + p0) * DH;
    const size_t koff = (((size_t)b * H + h) * C) * DH;
    const float* ebase = edge + ((size_t)b * P + p0) * C;

    const int krow = tid >> 3, kseg = tid & 7;

    auto load_chunk = [&](uint32_t stg, int cn) {
        cp16(stg + krow * AST + kseg * 16,
             kh + koff + (size_t)(cn + krow) * DH + kseg * 8);
        cp16(stg + 4608 + krow * AST + kseg * 16,
             vh + koff + (size_t)(cn + krow) * DH + kseg * 8);
#pragma unroll
        for (int i = 0; i < 4; i++) {
            int er = (tid + i * 256) >> 3;
            cp16(stg + 9216 + er * AST + kseg * 16,
                 ebase + (size_t)er * C + cn + kseg * 4);
        }
    };

#pragma unroll
    for (int i = 0; i < 8; i++) {
        int g = tid + i * 256;
        int arr = g >> 10, rem = g & 1023;
        int row = rem >> 3, seg = rem & 7;
        cp16(sbase + arr * 18432 + row * AST + seg * 16,
             (arr ? ql : qh) + qoff + (size_t)row * DH + seg * 8);
    }
    load_chunk(sbase + STG0, 0);
    CP_COMMIT();

    const int a_row = (lane & 7) + 8 * ((lane >> 3) & 1);
    const int a_colb = (lane >> 4) * 16;
    const int b4_row = ((lane >> 4) & 1) * 8 + (lane & 7);
    const int b4_colb = ((lane >> 3) & 1) * 16;
    const int r0 = lane >> 2;
    const int wr = wid * 16;
    const int c2 = (lane & 3) * 2;

    CP_WAIT0();
    __syncthreads();

    uint32_t qfh[4][4], qfl[4][4];
#pragma unroll
    for (int ks = 0; ks < 4; ks++) {
        uint32_t aoff = (uint32_t)(wr + a_row) * AST + a_colb + ks * 32;
        ldsm_x4(qfh[ks][0], qfh[ks][1], qfh[ks][2], qfh[ks][3], sbase + aoff);
        ldsm_x4(qfl[ks][0], qfl[ks][1], qfl[ks][2], qfl[ks][3],
                sbase + 18432 + aoff);
    }

    float m_r[2] = {-1e30f, -1e30f};
    float l_r[2] = {0.f, 0.f};
    float cacc[8][4];
#pragma unroll
    for (int i = 0; i < 8; i++)
#pragma unroll
        for (int j = 0; j < 4; j++) cacc[i][j] = 0.f;

    for (int ck = 0; ck < 16; ck++) {
        const uint32_t stgoff = STG0 + (uint32_t)(ck & 1) * STG_SZ;
        const uint32_t stg = sbase + stgoff;

        if (ck < 15) {
            load_chunk(sbase + STG0 + (uint32_t)((ck + 1) & 1) * STG_SZ,
                       (ck + 1) * 32);
            CP_COMMIT();
        }

        // ---- S = Q K^T (2-pass) ----
        float s[4][4];
#pragma unroll
        for (int i = 0; i < 4; i++)
#pragma unroll
            for (int j = 0; j < 4; j++) s[i][j] = 0.f;

#pragma unroll
        for (int ks = 0; ks < 4; ks++) {
            uint32_t bh2[4][2];
#pragma unroll
            for (int pi = 0; pi < 2; pi++) {
                uint32_t boff =
                    (uint32_t)(pi * 16 + b4_row) * AST + b4_colb + ks * 32;
                ldsm_x4(bh2[2 * pi][0], bh2[2 * pi][1],
                        bh2[2 * pi + 1][0], bh2[2 * pi + 1][1], stg + boff);
            }
#pragma unroll
            for (int ni = 0; ni < 4; ni++) mma16816(s[ni], qfh[ks], bh2[ni]);
#pragma unroll
            for (int ni = 0; ni < 4; ni++) mma16816(s[ni], qfl[ks], bh2[ni]);
        }

        // ---- online softmax (exp2 domain) ----
        float alpha[2];
#pragma unroll
        for (int rr = 0; rr < 2; rr++) {
            const float* ep = (const float*)(smem + stgoff + 9216 +
                                             (size_t)(wr + r0 + rr * 8) * AST) + c2;
            float ev[4][2];
            float mx = -1e30f;
#pragma unroll
            for (int j = 0; j < 4; j++) {
                float2 e2 = *(const float2*)(ep + j * 8);
                ev[j][0] = e2.x; ev[j][1] = e2.y;
                float s0 = (e2.x > 0.f) ? s[j][rr * 2] : -1e30f;
                float s1 = (e2.y > 0.f) ? s[j][rr * 2 + 1] : -1e30f;
                s[j][rr * 2] = s0; s[j][rr * 2 + 1] = s1;
                mx = fmaxf(mx, fmaxf(s0, s1));
            }
            mx = fmaxf(mx, __shfl_xor_sync(0xffffffffu, mx, 1));
            mx = fmaxf(mx, __shfl_xor_sync(0xffffffffu, mx, 2));
            float mn = fmaxf(m_r[rr], mx);
            alpha[rr] = exp2r(m_r[rr] - mn);
            m_r[rr] = mn;
            float ls = 0.f;
#pragma unroll
            for (int j = 0; j < 4; j++) {
                float ex0 = exp2r(s[j][rr * 2] - mn);
                float ex1 = exp2r(s[j][rr * 2 + 1] - mn);
                ls += ex0 + ex1;
                s[j][rr * 2] = ex0 * ev[j][0];
                s[j][rr * 2 + 1] = ex1 * ev[j][1];
            }
            ls += __shfl_xor_sync(0xffffffffu, ls, 1);
            ls += __shfl_xor_sync(0xffffffffu, ls, 2);
            l_r[rr] = l_r[rr] * alpha[rr] + ls;
        }

        // ---- rescale ctx, then ctx += P V (2-pass, V single fp16) ----
#pragma unroll
        for (int ni = 0; ni < 8; ni++) {
            cacc[ni][0] *= alpha[0]; cacc[ni][1] *= alpha[0];
            cacc[ni][2] *= alpha[1]; cacc[ni][3] *= alpha[1];
        }
#pragma unroll
        for (int ks = 0; ks < 2; ks++) {
            const float* t0 = s[2 * ks];
            const float* t1 = s[2 * ks + 1];
            uint32_t ap[4], alp[4];
#pragma unroll
            for (int q = 0; q < 4; q++) {
                const float* tt = (q < 2) ? t0 : t1;
                float v0 = tt[(q & 1) * 2], v1 = tt[(q & 1) * 2 + 1];
                uint32_t hp = pkhf(v0, v1);
                float2 hf = uphf(hp);
                ap[q] = hp;
                alp[q] = pkhf(v0 - hf.x, v1 - hf.y);
            }
            uint32_t vrow = (uint32_t)(ks * 16 + (lane & 15)) * AST;
            uint32_t vf[8][2];
#pragma unroll
            for (int ni = 0; ni < 8; ni++)
                ldsm_x2t(vf[ni][0], vf[ni][1], stg + 4608 + vrow + ni * 16);
#pragma unroll
            for (int ni = 0; ni < 8; ni++) mma16816(cacc[ni], ap, vf[ni]);
#pragma unroll
            for (int ni = 0; ni < 8; ni++) mma16816(cacc[ni], alp, vf[ni]);
        }

        if (ck < 15) {
            CP_WAIT0();
            __syncthreads();
        }
    }

    const float inv0 = 1.0f / l_r[0];
    const float inv1 = 1.0f / l_r[1];
    const int row0 = p0 + wr + r0;
#pragma unroll
    for (int ni = 0; ni < 8; ni++) {
        int dh = ni * 8 + c2;
        size_t base0 = ((size_t)b * P + row0) * D + h * DH + dh;
        float2 o0{cacc[ni][0] * inv0, cacc[ni][1] * inv0};
        float2 o1{cacc[ni][2] * inv1, cacc[ni][3] * inv1};
        *(float2*)(ctx + base0) = o0;
        *(float2*)(ctx + base0 + (size_t)8 * D) = o1;
    }
}

// =====================================================================
// LayerNorm over D=1024.
// =====================================================================
__global__ void __launch_bounds__(256) ln_kernel(
    const float* __restrict__ x, const float* __restrict__ gamma,
    const float* __restrict__ beta, float* __restrict__ out)
{
    __shared__ float rs1[8], rs2[8];
    const int row = blockIdx.x;
    const int tid = threadIdx.x;
    const float4 xv = *(const float4*)(x + (size_t)row * D + tid * 4);
    float s1 = xv.x + xv.y + xv.z + xv.w;
    float s2 = xv.x * xv.x + xv.y * xv.y + xv.z * xv.z + xv.w * xv.w;
#pragma unroll
    for (int o = 16; o; o >>= 1) {
        s1 += __shfl_xor_sync(0xffffffffu, s1, o);
        s2 += __shfl_xor_sync(0xffffffffu, s2, o);
    }
    if ((tid & 31) == 0) { rs1[tid >> 5] = s1; rs2[tid >> 5] = s2; }
    __syncthreads();
    if (tid < 32) {
        float t1 = (tid < 8) ? rs1[tid] : 0.f;
        float t2 = (tid < 8) ? rs2[tid] : 0.f;
#pragma unroll
        for (int o = 4; o; o >>= 1) {
            t1 += __shfl_xor_sync(0xffffffffu, t1, o);
            t2 += __shfl_xor_sync(0xffffffffu, t2, o);
        }
        if (tid == 0) { rs1[0] = t1; rs2[0] = t2; }
    }
    __syncthreads();
    const float mu = rs1[0] * (1.0f / D);
    const float var = fmaxf(rs2[0] * (1.0f / D) - mu * mu, 0.f);
    const float r = rsqrtf(var + 1e-6f);
    const float4 g = *(const float4*)(gamma + tid * 4);
    const float4 bt = *(const float4*)(beta + tid * 4);
    float4 o;
    o.x = (xv.x - mu) * r * g.x + bt.x;
    o.y = (xv.y - mu) * r * g.y + bt.y;
    o.z = (xv.z - mu) * r * g.z + bt.z;
    o.w = (xv.w - mu) * r * g.w + bt.w;
    *(float4*)(out + (size_t)row * D + tid * 4) = o;
}

// =====================================================================
extern "C" void kernel_launch(void* const* d_in, const int* in_sizes, int n_in,
                              void* d_out, int out_size)
{
    const float* para    = (const float*)d_in[0];
    const float* cluster = (const float*)d_in[1];
    const float* edge    = (const float*)d_in[2];
    const float* Wq = (const float*)d_in[3];
    const float* bq = (const float*)d_in[4];
    const float* Wk = (const float*)d_in[5];
    const float* bk = (const float*)d_in[6];
    const float* Wv = (const float*)d_in[7];
    const float* bv = (const float*)d_in[8];
    const float* gamma = (const float*)d_in[9];
    const float* beta  = (const float*)d_in[10];
    float* out = (float*)d_out;

    float* cp;
    __half *qhp, *qlp, *khp, *vhp;
    __half *pah, *pal, *clh, *cll, *wth;
    cudaGetSymbolAddress((void**)&cp, g_ctx);
    cudaGetSymbolAddress((void**)&qhp, g_qh);
    cudaGetSymbolAddress((void**)&qlp, g_ql);
    cudaGetSymbolAddress((void**)&khp, g_kh);
    cudaGetSymbolAddress((void**)&vhp, g_vh);
    cudaGetSymbolAddress((void**)&pah, g_pa_hi);
    cudaGetSymbolAddress((void**)&pal, g_pa_lo);
    cudaGetSymbolAddress((void**)&clh, g_cl_hi);
    cudaGetSymbolAddress((void**)&cll, g_cl_lo);
    cudaGetSymbolAddress((void**)&wth, g_wt_hi);

    cudaFuncSetAttribute(proj_mma,
                         cudaFuncAttributeMaxDynamicSharedMemorySize,
                         PROJ_SMEM_BYTES);
    cudaFuncSetAttribute(attn_mma,
                         cudaFuncAttributeMaxDynamicSharedMemorySize,
                         ATTN_SMEM_BYTES);

    prep_all<<<PREP_BLKS, 256>>>(para, cluster, Wq, Wk, Wv,
                                 pah, pal, clh, cll, wth);

    proj_mma<<<768, 256, PROJ_SMEM_BYTES>>>(pah, pal, clh, cll, wth,
                                            bq, bk, bv,
                                            qhp, qlp, khp, vhp);

    attn_mma<<<dim3(P / 128, H, B), 256, ATTN_SMEM_BYTES>>>(
        qhp, qlp, khp, vhp, edge, cp);

    ln_kernel<<<B * P, 256>>>(cp, gamma, beta, out);
}